// round 1
// baseline (speedup 1.0000x reference)
#include <cuda_runtime.h>
#include <cstdint>

#define LL 1024
#define BB 16
#define XD 512
#define YD 512
#define QDIM 64
#define ND 4
#define HL 128
#define MTOT (LL*BB)      // 16384
#define RSQRT512 0.04419417382415922f

// -------- scratch (device globals; no allocation allowed) --------
__device__ float g_Q  [ND*BB*LL*QDIM];        // [d][b][l][q]  16 MB
__device__ float g_sq [ND*BB*LL];             // [d][b][l]
__device__ float g_h  [MTOT*HL];              // [m=(l,b)][h]   8 MB
__device__ float g_Sin[BB*LL*YD];             // [b][l][y]     32 MB
__device__ float g_E  [(size_t)BB*LL*LL];     // [b][i][j]     64 MB
__device__ float g_R  [BB*LL];                // rowsums

// ============================================================
// K1: Qins = X @ Wq^T + bq   (M=16384, N=256, K=512)
// scatter to g_Q[d][b][l][q]
// ============================================================
__global__ __launch_bounds__(256) void k1_qproj(const float* __restrict__ X,
                                                const float* __restrict__ Wq,
                                                const float* __restrict__ bq) {
    __shared__ float As[16][68];
    __shared__ float Bs[16][68];
    const int tid = threadIdx.x;
    const int row0 = blockIdx.y * 64, col0 = blockIdx.x * 64;
    const int lm = tid >> 2, lk4 = (tid & 3) * 4;
    const int ty = tid >> 4, tx = tid & 15;
    float acc[4][4] = {};
    for (int k0 = 0; k0 < XD; k0 += 16) {
        float4 a = *(const float4*)&X[(size_t)(row0 + lm) * XD + k0 + lk4];
        As[lk4+0][lm] = a.x; As[lk4+1][lm] = a.y; As[lk4+2][lm] = a.z; As[lk4+3][lm] = a.w;
        float4 w = *(const float4*)&Wq[(size_t)(col0 + lm) * XD + k0 + lk4];
        Bs[lk4+0][lm] = w.x; Bs[lk4+1][lm] = w.y; Bs[lk4+2][lm] = w.z; Bs[lk4+3][lm] = w.w;
        __syncthreads();
        #pragma unroll
        for (int k = 0; k < 16; k++) {
            float4 av = *(float4*)&As[k][ty*4];
            float4 bv = *(float4*)&Bs[k][tx*4];
            acc[0][0] += av.x*bv.x; acc[0][1] += av.x*bv.y; acc[0][2] += av.x*bv.z; acc[0][3] += av.x*bv.w;
            acc[1][0] += av.y*bv.x; acc[1][1] += av.y*bv.y; acc[1][2] += av.y*bv.z; acc[1][3] += av.y*bv.w;
            acc[2][0] += av.z*bv.x; acc[2][1] += av.z*bv.y; acc[2][2] += av.z*bv.z; acc[2][3] += av.z*bv.w;
            acc[3][0] += av.w*bv.x; acc[3][1] += av.w*bv.y; acc[3][2] += av.w*bv.z; acc[3][3] += av.w*bv.w;
        }
        __syncthreads();
    }
    // epilogue: +bq, scatter. Within a block, d is fixed (col0 multiple of 64, N tile == one d)
    const int d = col0 >> 6;
    const int qb = tx * 4;  // q base (col0 % 64 == 0)
    #pragma unroll
    for (int i = 0; i < 4; i++) {
        int m = row0 + ty*4 + i;
        int l = m >> 4, b = m & 15;
        float4 v;
        v.x = acc[i][0] + bq[col0 + qb + 0];
        v.y = acc[i][1] + bq[col0 + qb + 1];
        v.z = acc[i][2] + bq[col0 + qb + 2];
        v.w = acc[i][3] + bq[col0 + qb + 3];
        *(float4*)&g_Q[(((size_t)d*BB + b)*LL + l)*QDIM + qb] = v;
    }
}

// ============================================================
// Ksq: sq[d][b][l] = sum_q Q^2  (one warp per row of 64)
// ============================================================
__global__ __launch_bounds__(256) void ksq() {
    const int warp = threadIdx.x >> 5, lane = threadIdx.x & 31;
    const size_t row = (size_t)blockIdx.x * 8 + warp;   // 0..65535
    const float* p = g_Q + row * QDIM;
    float a = p[lane], b = p[lane + 32];
    float s = a*a + b*b;
    #pragma unroll
    for (int o = 16; o; o >>= 1) s += __shfl_xor_sync(0xffffffffu, s, o);
    if (lane == 0) g_sq[row] = s;
}

// ============================================================
// K2a: h = sigmoid(X @ Wh^T + bh)   (M=16384, N=128, K=512)
// ============================================================
__global__ __launch_bounds__(256) void k2a_h(const float* __restrict__ X,
                                             const float* __restrict__ Wh,
                                             const float* __restrict__ bh) {
    __shared__ float As[16][68];
    __shared__ float Bs[16][68];
    const int tid = threadIdx.x;
    const int row0 = blockIdx.y * 64, col0 = blockIdx.x * 64;
    const int lm = tid >> 2, lk4 = (tid & 3) * 4;
    const int ty = tid >> 4, tx = tid & 15;
    float acc[4][4] = {};
    for (int k0 = 0; k0 < XD; k0 += 16) {
        float4 a = *(const float4*)&X[(size_t)(row0 + lm) * XD + k0 + lk4];
        As[lk4+0][lm] = a.x; As[lk4+1][lm] = a.y; As[lk4+2][lm] = a.z; As[lk4+3][lm] = a.w;
        float4 w = *(const float4*)&Wh[(size_t)(col0 + lm) * XD + k0 + lk4];
        Bs[lk4+0][lm] = w.x; Bs[lk4+1][lm] = w.y; Bs[lk4+2][lm] = w.z; Bs[lk4+3][lm] = w.w;
        __syncthreads();
        #pragma unroll
        for (int k = 0; k < 16; k++) {
            float4 av = *(float4*)&As[k][ty*4];
            float4 bv = *(float4*)&Bs[k][tx*4];
            acc[0][0] += av.x*bv.x; acc[0][1] += av.x*bv.y; acc[0][2] += av.x*bv.z; acc[0][3] += av.x*bv.w;
            acc[1][0] += av.y*bv.x; acc[1][1] += av.y*bv.y; acc[1][2] += av.y*bv.z; acc[1][3] += av.y*bv.w;
            acc[2][0] += av.z*bv.x; acc[2][1] += av.z*bv.y; acc[2][2] += av.z*bv.z; acc[2][3] += av.z*bv.w;
            acc[3][0] += av.w*bv.x; acc[3][1] += av.w*bv.y; acc[3][2] += av.w*bv.z; acc[3][3] += av.w*bv.w;
        }
        __syncthreads();
    }
    const int nb = col0 + tx * 4;
    #pragma unroll
    for (int i = 0; i < 4; i++) {
        int m = row0 + ty*4 + i;
        float4 v;
        v.x = 1.f / (1.f + __expf(-(acc[i][0] + bh[nb+0])));
        v.y = 1.f / (1.f + __expf(-(acc[i][1] + bh[nb+1])));
        v.z = 1.f / (1.f + __expf(-(acc[i][2] + bh[nb+2])));
        v.w = 1.f / (1.f + __expf(-(acc[i][3] + bh[nb+3])));
        *(float4*)&g_h[(size_t)m * HL + nb] = v;
    }
}

// ============================================================
// K2b: Sin = h @ Ws^T + bs   (M=16384, N=512, K=128) -> g_Sin[b][l][y]
// ============================================================
__global__ __launch_bounds__(256) void k2b_sin(const float* __restrict__ Ws,
                                               const float* __restrict__ bs) {
    __shared__ float As[16][68];
    __shared__ float Bs[16][68];
    const int tid = threadIdx.x;
    const int row0 = blockIdx.y * 64, col0 = blockIdx.x * 64;
    const int lm = tid >> 2, lk4 = (tid & 3) * 4;
    const int ty = tid >> 4, tx = tid & 15;
    float acc[4][4] = {};
    for (int k0 = 0; k0 < HL; k0 += 16) {
        float4 a = *(const float4*)&g_h[(size_t)(row0 + lm) * HL + k0 + lk4];
        As[lk4+0][lm] = a.x; As[lk4+1][lm] = a.y; As[lk4+2][lm] = a.z; As[lk4+3][lm] = a.w;
        float4 w = *(const float4*)&Ws[(size_t)(col0 + lm) * HL + k0 + lk4];
        Bs[lk4+0][lm] = w.x; Bs[lk4+1][lm] = w.y; Bs[lk4+2][lm] = w.z; Bs[lk4+3][lm] = w.w;
        __syncthreads();
        #pragma unroll
        for (int k = 0; k < 16; k++) {
            float4 av = *(float4*)&As[k][ty*4];
            float4 bv = *(float4*)&Bs[k][tx*4];
            acc[0][0] += av.x*bv.x; acc[0][1] += av.x*bv.y; acc[0][2] += av.x*bv.z; acc[0][3] += av.x*bv.w;
            acc[1][0] += av.y*bv.x; acc[1][1] += av.y*bv.y; acc[1][2] += av.y*bv.z; acc[1][3] += av.y*bv.w;
            acc[2][0] += av.z*bv.x; acc[2][1] += av.z*bv.y; acc[2][2] += av.z*bv.z; acc[2][3] += av.z*bv.w;
            acc[3][0] += av.w*bv.x; acc[3][1] += av.w*bv.y; acc[3][2] += av.w*bv.z; acc[3][3] += av.w*bv.w;
        }
        __syncthreads();
    }
    const int nb = col0 + tx * 4;
    #pragma unroll
    for (int i = 0; i < 4; i++) {
        int m = row0 + ty*4 + i;
        int l = m >> 4, b = m & 15;
        float4 v;
        v.x = acc[i][0] + bs[nb+0];
        v.y = acc[i][1] + bs[nb+1];
        v.z = acc[i][2] + bs[nb+2];
        v.w = acc[i][3] + bs[nb+3];
        *(float4*)&g_Sin[((size_t)b*LL + l)*YD + nb] = v;
    }
}

// ============================================================
// K3: fused pairwise-distance logits -> E = exp(sum_d c_d*dist_d/sqrt(512)+mask)
// grid (jT=16, iT=16, b=16), 64x64 tiles
// ============================================================
__global__ __launch_bounds__(256) void k3_logits(const float* __restrict__ mask) {
    __shared__ float Qis[64][68];   // [q][i]
    __shared__ float Qjs[64][68];   // [q][j]
    const int bI = blockIdx.z;
    const int i0 = blockIdx.y * 64, j0 = blockIdx.x * 64;
    const int tid = threadIdx.x;
    const int ty = tid >> 4, tx = tid & 15;
    const int lr = tid >> 4;          // 0..15
    const int lc4 = (tid & 15) * 4;   // 0..60
    float logit[4][4] = {};
    for (int d = 0; d < ND; d++) {
        const float* Pi = g_Q + (((size_t)d*BB + bI)*LL + i0) * QDIM;
        const float* Pj = g_Q + (((size_t)d*BB + bI)*LL + j0) * QDIM;
        #pragma unroll
        for (int rr = 0; rr < 4; rr++) {
            int r = lr + rr * 16;
            float4 v = *(const float4*)&Pi[(size_t)r * QDIM + lc4];
            Qis[lc4+0][r] = v.x; Qis[lc4+1][r] = v.y; Qis[lc4+2][r] = v.z; Qis[lc4+3][r] = v.w;
            float4 w = *(const float4*)&Pj[(size_t)r * QDIM + lc4];
            Qjs[lc4+0][r] = w.x; Qjs[lc4+1][r] = w.y; Qjs[lc4+2][r] = w.z; Qjs[lc4+3][r] = w.w;
        }
        __syncthreads();
        float G[4][4] = {};
        #pragma unroll
        for (int k = 0; k < QDIM; k++) {
            float4 av = *(float4*)&Qis[k][ty*4];
            float4 bv = *(float4*)&Qjs[k][tx*4];
            G[0][0] += av.x*bv.x; G[0][1] += av.x*bv.y; G[0][2] += av.x*bv.z; G[0][3] += av.x*bv.w;
            G[1][0] += av.y*bv.x; G[1][1] += av.y*bv.y; G[1][2] += av.y*bv.z; G[1][3] += av.y*bv.w;
            G[2][0] += av.z*bv.x; G[2][1] += av.z*bv.y; G[2][2] += av.z*bv.z; G[2][3] += av.z*bv.w;
            G[3][0] += av.w*bv.x; G[3][1] += av.w*bv.y; G[3][2] += av.w*bv.z; G[3][3] += av.w*bv.w;
        }
        const float sgn = (d & 1) ? -1.f : 1.f;
        const float* sqb = g_sq + ((size_t)d*BB + bI) * LL;
        #pragma unroll
        for (int i = 0; i < 4; i++) {
            int gi = i0 + ty*4 + i;
            float sqi = sqb[gi];
            #pragma unroll
            for (int j = 0; j < 4; j++) {
                int gj = j0 + tx*4 + j;
                float sqj = sqb[gj];
                float d2 = fmaxf(sqi + sqj - 2.f * G[i][j], 0.f);
                float dist = (gi == gj) ? 0.f : sqrtf(d2);
                logit[i][j] += sgn * dist;
            }
        }
        __syncthreads();
    }
    #pragma unroll
    for (int i = 0; i < 4; i++) {
        int gi = i0 + ty*4 + i;
        int gjb = j0 + tx*4;
        float4 mv = *(const float4*)&mask[(size_t)gi * LL + gjb];
        float4 e;
        e.x = __expf(logit[i][0] * RSQRT512 + mv.x);
        e.y = __expf(logit[i][1] * RSQRT512 + mv.y);
        e.z = __expf(logit[i][2] * RSQRT512 + mv.z);
        e.w = __expf(logit[i][3] * RSQRT512 + mv.w);
        *(float4*)&g_E[((size_t)bI*LL + gi)*LL + gjb] = e;
    }
}

// ============================================================
// K3b: rowsums of E (one warp per row of 1024)
// ============================================================
__global__ __launch_bounds__(256) void k3b_rowsum() {
    const int warp = threadIdx.x >> 5, lane = threadIdx.x & 31;
    const int row = blockIdx.x * 8 + warp;   // 0..16383
    const float* p = g_E + (size_t)row * LL;
    float s = 0.f;
    #pragma unroll 8
    for (int t = lane; t < LL; t += 32) s += p[t];
    #pragma unroll
    for (int o = 16; o; o >>= 1) s += __shfl_xor_sync(0xffffffffu, s, o);
    if (lane == 0) g_R[row] = s;
}

// ============================================================
// K4: Sout[b] = diag(1/R) * E[b] @ Sin[b]   (per-b 1024x512x1024 GEMM)
// grid (yT=8, iT=16, b=16)
// ============================================================
__global__ __launch_bounds__(256) void k4_pv(float* __restrict__ out) {
    __shared__ float As[16][68];
    __shared__ float Bs[16][68];
    const int b = blockIdx.z;
    const int row0 = blockIdx.y * 64, col0 = blockIdx.x * 64;
    const float* E = g_E + (size_t)b * LL * LL;
    const float* S = g_Sin + (size_t)b * LL * YD;
    const int tid = threadIdx.x;
    const int lm = tid >> 2, lk4 = (tid & 3) * 4;    // A loader (transpose)
    const int bk = tid >> 4, bn4 = (tid & 15) * 4;   // B loader (direct)
    const int ty = tid >> 4, tx = tid & 15;
    float acc[4][4] = {};
    for (int k0 = 0; k0 < LL; k0 += 16) {
        float4 a = *(const float4*)&E[(size_t)(row0 + lm) * LL + k0 + lk4];
        As[lk4+0][lm] = a.x; As[lk4+1][lm] = a.y; As[lk4+2][lm] = a.z; As[lk4+3][lm] = a.w;
        *(float4*)&Bs[bk][bn4] = *(const float4*)&S[(size_t)(k0 + bk) * YD + col0 + bn4];
        __syncthreads();
        #pragma unroll
        for (int k = 0; k < 16; k++) {
            float4 av = *(float4*)&As[k][ty*4];
            float4 bv = *(float4*)&Bs[k][tx*4];
            acc[0][0] += av.x*bv.x; acc[0][1] += av.x*bv.y; acc[0][2] += av.x*bv.z; acc[0][3] += av.x*bv.w;
            acc[1][0] += av.y*bv.x; acc[1][1] += av.y*bv.y; acc[1][2] += av.y*bv.z; acc[1][3] += av.y*bv.w;
            acc[2][0] += av.z*bv.x; acc[2][1] += av.z*bv.y; acc[2][2] += av.z*bv.z; acc[2][3] += av.z*bv.w;
            acc[3][0] += av.w*bv.x; acc[3][1] += av.w*bv.y; acc[3][2] += av.w*bv.z; acc[3][3] += av.w*bv.w;
        }
        __syncthreads();
    }
    #pragma unroll
    for (int i = 0; i < 4; i++) {
        int row = row0 + ty*4 + i;
        float rinv = 1.f / g_R[b * LL + row];
        float4 v;
        v.x = acc[i][0] * rinv; v.y = acc[i][1] * rinv;
        v.z = acc[i][2] * rinv; v.w = acc[i][3] * rinv;
        *(float4*)&out[((size_t)b*LL + row)*YD + col0 + tx*4] = v;
    }
}

// ============================================================
// K5: temp_Qins[b][q] = mean over (d,l) of Q
// ============================================================
__global__ __launch_bounds__(256) void k5_tq(float* __restrict__ out2) {
    const int b = blockIdx.x;
    const int t = threadIdx.x;
    const int q = t & 63, part = t >> 6;
    float s = 0.f;
    for (int d = 0; d < ND; d++) {
        const float* base = g_Q + (((size_t)d*BB + b)*LL) * QDIM;
        for (int l = part; l < LL; l += 4) s += base[(size_t)l * QDIM + q];
    }
    __shared__ float red[256];
    red[t] = s;
    __syncthreads();
    if (part == 0)
        out2[b * QDIM + q] = (red[q] + red[64+q] + red[128+q] + red[192+q]) * (1.f / (ND * (float)LL));
}

// ============================================================
extern "C" void kernel_launch(void* const* d_in, const int* in_sizes, int n_in,
                              void* d_out, int out_size) {
    const float* X    = (const float*)d_in[0];
    const float* mask = (const float*)d_in[1];
    const float* Wq   = (const float*)d_in[2];
    const float* bq   = (const float*)d_in[3];
    const float* Wh   = (const float*)d_in[4];
    const float* bh   = (const float*)d_in[5];
    const float* Ws   = (const float*)d_in[6];
    const float* bs   = (const float*)d_in[7];
    float* out = (float*)d_out;

    k1_qproj<<<dim3(4, 256), 256>>>(X, Wq, bq);
    ksq<<<8192, 256>>>();
    k2a_h<<<dim3(2, 256), 256>>>(X, Wh, bh);
    k2b_sin<<<dim3(8, 256), 256>>>(Ws, bs);
    k3_logits<<<dim3(16, 16, 16), 256>>>(mask);
    k3b_rowsum<<<2048, 256>>>();
    k4_pv<<<dim3(8, 16, 16), 256>>>(out);
    k5_tq<<<16, 256>>>(out + (size_t)BB * LL * YD);
}

// round 3
// speedup vs baseline: 1.6364x; 1.6364x over previous
#include <cuda_runtime.h>
#include <cstdint>

#define LL 1024
#define BB 16
#define XD 512
#define YD 512
#define QDIM 64
#define ND 4
#define HL 128
#define MTOT (LL*BB)      // 16384
#define RSQRT512 0.04419417382415922f

// -------- scratch (device globals; no allocation allowed) --------
__device__ float g_Q  [ND*BB*LL*QDIM];        // [d][b][l][q]
__device__ float g_sq [ND*BB*LL];             // [d][b][l]
__device__ float g_h  [MTOT*HL];              // [m][h]
__device__ float g_Sin[BB*LL*YD];             // [b][l][y]
__device__ float g_E  [(size_t)BB*LL*LL];     // [b][i][j]
__device__ float g_R  [BB*LL];                // rowsums

// ---------------- tf32 mma tile machinery ----------------
#define BM 128
#define BN 128
#define BK 16
#define AS_LD 20          // 128 rows x 20 stride (conflict-free for frag loads)
#define BS_LD 136         // 16 k-rows x 136 stride (stride%32==8 -> conflict-free)
#define SMEM_FLOATS (BM*AS_LD + BK*BS_LD)

__device__ __forceinline__ uint32_t f2tf(float f) {
    uint32_t r; asm("cvt.rna.tf32.f32 %0, %1;" : "=r"(r) : "f"(f)); return r;
}

__device__ __forceinline__ void mma_tf32(float c[4], const uint32_t a[4], const uint32_t b[2]) {
    asm volatile("mma.sync.aligned.m16n8k8.row.col.f32.tf32.tf32.f32 "
        "{%0,%1,%2,%3}, {%4,%5,%6,%7}, {%8,%9}, {%0,%1,%2,%3};"
        : "+f"(c[0]), "+f"(c[1]), "+f"(c[2]), "+f"(c[3])
        : "r"(a[0]), "r"(a[1]), "r"(a[2]), "r"(a[3]), "r"(b[0]), "r"(b[1]));
}

// Computes acc[2][8][4] += A(128xK, row-major lda) @ B
//   BT=true : Bg is [N][K] row-major (weights / Q^T)   -> B[k][n] = Bg[n][k]
//   BT=false: Bg is [K][N] row-major (activations)     -> B[k][n] = Bg[k][n]
// Warp layout: wm = (warp&3)*32 rows, wn = (warp>>2)*64 cols; per-warp 32x64
template<bool BT>
__device__ __forceinline__ void gemm_mainloop(const float* __restrict__ A, int lda,
                                              const float* __restrict__ Bg, int ldb,
                                              int K, float acc[2][8][4],
                                              float* As, float* Bs)
{
    const int tid = threadIdx.x;
    const int lane = tid & 31, warp = tid >> 5;
    const int wm = (warp & 3) * 32, wn = (warp >> 2) * 64;
    const int qr = lane >> 2, qc = lane & 3;
    for (int k0 = 0; k0 < K; k0 += BK) {
        #pragma unroll
        for (int i = 0; i < 2; i++) {
            int idx = tid * 2 + i;
            int row = idx >> 2, k4 = (idx & 3) * 4;
            float4 v = *(const float4*)&A[(size_t)row * lda + k0 + k4];
            As[row*AS_LD + k4 + 0] = __uint_as_float(f2tf(v.x));
            As[row*AS_LD + k4 + 1] = __uint_as_float(f2tf(v.y));
            As[row*AS_LD + k4 + 2] = __uint_as_float(f2tf(v.z));
            As[row*AS_LD + k4 + 3] = __uint_as_float(f2tf(v.w));
        }
        if (BT) {
            #pragma unroll
            for (int i = 0; i < 2; i++) {
                int idx = tid * 2 + i;
                int n = idx >> 2, k4 = (idx & 3) * 4;
                float4 v = *(const float4*)&Bg[(size_t)n * ldb + k0 + k4];
                Bs[(k4+0)*BS_LD + n] = __uint_as_float(f2tf(v.x));
                Bs[(k4+1)*BS_LD + n] = __uint_as_float(f2tf(v.y));
                Bs[(k4+2)*BS_LD + n] = __uint_as_float(f2tf(v.z));
                Bs[(k4+3)*BS_LD + n] = __uint_as_float(f2tf(v.w));
            }
        } else {
            #pragma unroll
            for (int i = 0; i < 2; i++) {
                int idx = tid * 2 + i;
                int kk = idx >> 5, n4 = (idx & 31) * 4;
                float4 v = *(const float4*)&Bg[(size_t)(k0 + kk) * ldb + n4];
                Bs[kk*BS_LD + n4 + 0] = __uint_as_float(f2tf(v.x));
                Bs[kk*BS_LD + n4 + 1] = __uint_as_float(f2tf(v.y));
                Bs[kk*BS_LD + n4 + 2] = __uint_as_float(f2tf(v.z));
                Bs[kk*BS_LD + n4 + 3] = __uint_as_float(f2tf(v.w));
            }
        }
        __syncthreads();
        #pragma unroll
        for (int kk = 0; kk < 2; kk++) {
            uint32_t af[2][4];
            #pragma unroll
            for (int m = 0; m < 2; m++) {
                int r = wm + m*16 + qr;
                int c = kk*8 + qc;
                af[m][0] = __float_as_uint(As[r*AS_LD + c]);
                af[m][1] = __float_as_uint(As[(r+8)*AS_LD + c]);
                af[m][2] = __float_as_uint(As[r*AS_LD + c + 4]);
                af[m][3] = __float_as_uint(As[(r+8)*AS_LD + c + 4]);
            }
            uint32_t bf[8][2];
            #pragma unroll
            for (int n = 0; n < 8; n++) {
                int cn = wn + n*8 + qr;
                int rk = kk*8 + qc;
                bf[n][0] = __float_as_uint(Bs[rk*BS_LD + cn]);
                bf[n][1] = __float_as_uint(Bs[(rk+4)*BS_LD + cn]);
            }
            #pragma unroll
            for (int m = 0; m < 2; m++)
                #pragma unroll
                for (int n = 0; n < 8; n++)
                    mma_tf32(acc[m][n], af[m], bf[n]);
        }
        __syncthreads();
    }
}

// ============================================================
// K1: Qins = X @ Wq^T + bq   (M=16384, N=256, K=512) -> g_Q[d][b][l][q]
// ============================================================
__global__ __launch_bounds__(256, 2) void k1_qproj(const float* __restrict__ X,
                                                   const float* __restrict__ Wq,
                                                   const float* __restrict__ bq) {
    __shared__ float smem[SMEM_FLOATS];
    const int row0 = blockIdx.y * BM, col0 = blockIdx.x * BN;
    float acc[2][8][4] = {};
    gemm_mainloop<true>(X + (size_t)row0 * XD, XD, Wq + (size_t)col0 * XD, XD, XD,
                        acc, smem, smem + BM*AS_LD);
    const int lane = threadIdx.x & 31, warp = threadIdx.x >> 5;
    const int wm = (warp & 3) * 32, wn = (warp >> 2) * 64;
    const int qr = lane >> 2, qc = lane & 3;
    #pragma unroll
    for (int m = 0; m < 2; m++)
        #pragma unroll
        for (int rr = 0; rr < 2; rr++) {
            int mrow = row0 + wm + m*16 + qr + rr*8;
            int l = mrow >> 4, b = mrow & 15;
            #pragma unroll
            for (int n = 0; n < 8; n++) {
                int cg = col0 + wn + n*8 + 2*qc;   // even; pair stays within one d
                int d = cg >> 6, q = cg & 63;
                float2 v;
                v.x = acc[m][n][rr*2+0] + bq[cg];
                v.y = acc[m][n][rr*2+1] + bq[cg+1];
                *(float2*)&g_Q[(((size_t)d*BB + b)*LL + l)*QDIM + q] = v;
            }
        }
}

// ============================================================
// Ksq: sq[d][b][l] = sum_q Q^2
// ============================================================
__global__ __launch_bounds__(256) void ksq() {
    const int warp = threadIdx.x >> 5, lane = threadIdx.x & 31;
    const size_t row = (size_t)blockIdx.x * 8 + warp;
    const float* p = g_Q + row * QDIM;
    float a = p[lane], b = p[lane + 32];
    float s = a*a + b*b;
    #pragma unroll
    for (int o = 16; o; o >>= 1) s += __shfl_xor_sync(0xffffffffu, s, o);
    if (lane == 0) g_sq[row] = s;
}

// ============================================================
// K2a: h = sigmoid(X @ Wh^T + bh)   (M=16384, N=128, K=512)
// ============================================================
__global__ __launch_bounds__(256, 2) void k2a_h(const float* __restrict__ X,
                                                const float* __restrict__ Wh,
                                                const float* __restrict__ bh) {
    __shared__ float smem[SMEM_FLOATS];
    const int row0 = blockIdx.y * BM;
    float acc[2][8][4] = {};
    gemm_mainloop<true>(X + (size_t)row0 * XD, XD, Wh, XD, XD,
                        acc, smem, smem + BM*AS_LD);
    const int lane = threadIdx.x & 31, warp = threadIdx.x >> 5;
    const int wm = (warp & 3) * 32, wn = (warp >> 2) * 64;
    const int qr = lane >> 2, qc = lane & 3;
    #pragma unroll
    for (int m = 0; m < 2; m++)
        #pragma unroll
        for (int rr = 0; rr < 2; rr++) {
            int mrow = row0 + wm + m*16 + qr + rr*8;
            #pragma unroll
            for (int n = 0; n < 8; n++) {
                int cg = wn + n*8 + 2*qc;
                float2 v;
                v.x = 1.f / (1.f + __expf(-(acc[m][n][rr*2+0] + bh[cg])));
                v.y = 1.f / (1.f + __expf(-(acc[m][n][rr*2+1] + bh[cg+1])));
                *(float2*)&g_h[(size_t)mrow * HL + cg] = v;
            }
        }
}

// ============================================================
// K2b: Sin = h @ Ws^T + bs   (M=16384, N=512, K=128) -> g_Sin[b][l][y]
// ============================================================
__global__ __launch_bounds__(256, 2) void k2b_sin(const float* __restrict__ Ws,
                                                  const float* __restrict__ bs) {
    __shared__ float smem[SMEM_FLOATS];
    const int row0 = blockIdx.y * BM, col0 = blockIdx.x * BN;
    float acc[2][8][4] = {};
    gemm_mainloop<true>(g_h + (size_t)row0 * HL, HL, Ws + (size_t)col0 * HL, HL, HL,
                        acc, smem, smem + BM*AS_LD);
    const int lane = threadIdx.x & 31, warp = threadIdx.x >> 5;
    const int wm = (warp & 3) * 32, wn = (warp >> 2) * 64;
    const int qr = lane >> 2, qc = lane & 3;
    #pragma unroll
    for (int m = 0; m < 2; m++)
        #pragma unroll
        for (int rr = 0; rr < 2; rr++) {
            int mrow = row0 + wm + m*16 + qr + rr*8;
            int l = mrow >> 4, b = mrow & 15;
            #pragma unroll
            for (int n = 0; n < 8; n++) {
                int cg = col0 + wn + n*8 + 2*qc;
                float2 v;
                v.x = acc[m][n][rr*2+0] + bs[cg];
                v.y = acc[m][n][rr*2+1] + bs[cg+1];
                *(float2*)&g_Sin[((size_t)b*LL + l)*YD + cg] = v;
            }
        }
}

// ============================================================
// K3: fused pairwise-distance logits -> E = exp(sum_d sgn*dist/sqrt(512)+mask)
// 128x128 tiles, grid (8, 8, 16)
// ============================================================
__global__ __launch_bounds__(256) void k3_logits(const float* __restrict__ mask) {
    __shared__ float smem[SMEM_FLOATS];
    const int bI = blockIdx.z;
    const int i0 = blockIdx.y * BM, j0 = blockIdx.x * BN;
    const int lane = threadIdx.x & 31, warp = threadIdx.x >> 5;
    const int wm = (warp & 3) * 32, wn = (warp >> 2) * 64;
    const int qr = lane >> 2, qc = lane & 3;
    float logit[2][8][4] = {};
    #pragma unroll
    for (int d = 0; d < ND; d++) {
        float acc[2][8][4] = {};
        const float* Qb = g_Q + (((size_t)d*BB + bI)*LL) * QDIM;
        gemm_mainloop<true>(Qb + (size_t)i0 * QDIM, QDIM, Qb + (size_t)j0 * QDIM, QDIM, QDIM,
                            acc, smem, smem + BM*AS_LD);
        const float sgn = (d & 1) ? -1.f : 1.f;
        const float* sqb = g_sq + ((size_t)d*BB + bI) * LL;
        #pragma unroll
        for (int m = 0; m < 2; m++)
            #pragma unroll
            for (int rr = 0; rr < 2; rr++) {
                int gi = i0 + wm + m*16 + qr + rr*8;
                float sqi = sqb[gi];
                #pragma unroll
                for (int n = 0; n < 8; n++) {
                    int gj = j0 + wn + n*8 + 2*qc;
                    float sqj0 = sqb[gj], sqj1 = sqb[gj+1];
                    float d20 = fmaxf(sqi + sqj0 - 2.f*acc[m][n][rr*2+0], 0.f);
                    float d21 = fmaxf(sqi + sqj1 - 2.f*acc[m][n][rr*2+1], 0.f);
                    float dist0 = (gi == gj)   ? 0.f : sqrtf(d20);
                    float dist1 = (gi == gj+1) ? 0.f : sqrtf(d21);
                    logit[m][n][rr*2+0] += sgn * dist0;
                    logit[m][n][rr*2+1] += sgn * dist1;
                }
            }
    }
    #pragma unroll
    for (int m = 0; m < 2; m++)
        #pragma unroll
        for (int rr = 0; rr < 2; rr++) {
            int gi = i0 + wm + m*16 + qr + rr*8;
            #pragma unroll
            for (int n = 0; n < 8; n++) {
                int gj = j0 + wn + n*8 + 2*qc;
                float2 mv = *(const float2*)&mask[(size_t)gi * LL + gj];
                float2 e;
                e.x = __expf(logit[m][n][rr*2+0] * RSQRT512 + mv.x);
                e.y = __expf(logit[m][n][rr*2+1] * RSQRT512 + mv.y);
                *(float2*)&g_E[((size_t)bI*LL + gi)*LL + gj] = e;
            }
        }
}

// ============================================================
// K3b: rowsums of E (one warp per row)
// ============================================================
__global__ __launch_bounds__(256) void k3b_rowsum() {
    const int warp = threadIdx.x >> 5, lane = threadIdx.x & 31;
    const int row = blockIdx.x * 8 + warp;
    const float4* p = (const float4*)(g_E + (size_t)row * LL);
    float s = 0.f;
    #pragma unroll 4
    for (int t = lane; t < LL/4; t += 32) {
        float4 v = p[t];
        s += (v.x + v.y) + (v.z + v.w);
    }
    #pragma unroll
    for (int o = 16; o; o >>= 1) s += __shfl_xor_sync(0xffffffffu, s, o);
    if (lane == 0) g_R[row] = s;
}

// ============================================================
// K4: Sout[b] = diag(1/R) * E[b] @ Sin[b]   (1024x512x1024 per b)
// ============================================================
__global__ __launch_bounds__(256, 2) void k4_pv(float* __restrict__ out) {
    __shared__ float smem[SMEM_FLOATS];
    const int b = blockIdx.z;
    const int row0 = blockIdx.y * BM, col0 = blockIdx.x * BN;
    float acc[2][8][4] = {};
    gemm_mainloop<false>(g_E + (size_t)b*LL*LL + (size_t)row0 * LL, LL,
                         g_Sin + (size_t)b*LL*YD + col0, YD, LL,
                         acc, smem, smem + BM*AS_LD);
    const int lane = threadIdx.x & 31, warp = threadIdx.x >> 5;
    const int wm = (warp & 3) * 32, wn = (warp >> 2) * 64;
    const int qr = lane >> 2, qc = lane & 3;
    #pragma unroll
    for (int m = 0; m < 2; m++)
        #pragma unroll
        for (int rr = 0; rr < 2; rr++) {
            int row = row0 + wm + m*16 + qr + rr*8;
            float rinv = 1.f / g_R[b*LL + row];
            #pragma unroll
            for (int n = 0; n < 8; n++) {
                int col = col0 + wn + n*8 + 2*qc;
                float2 v;
                v.x = acc[m][n][rr*2+0] * rinv;
                v.y = acc[m][n][rr*2+1] * rinv;
                *(float2*)&out[((size_t)b*LL + row)*YD + col] = v;
            }
        }
}

// ============================================================
// K5: temp_Qins[b][q] = mean over (d,l) of Q
// ============================================================
__global__ __launch_bounds__(256) void k5_tq(float* __restrict__ out2) {
    const int b = blockIdx.x;
    const int t = threadIdx.x;
    const int q = t & 63, part = t >> 6;
    float s = 0.f;
    for (int d = 0; d < ND; d++) {
        const float* base = g_Q + (((size_t)d*BB + b)*LL) * QDIM;
        for (int l = part; l < LL; l += 4) s += base[(size_t)l * QDIM + q];
    }
    __shared__ float red[256];
    red[t] = s;
    __syncthreads();
    if (part == 0)
        out2[b * QDIM + q] = (red[q] + red[64+q] + red[128+q] + red[192+q]) * (1.f / (ND * (float)LL));
}

// ============================================================
extern "C" void kernel_launch(void* const* d_in, const int* in_sizes, int n_in,
                              void* d_out, int out_size) {
    const float* X    = (const float*)d_in[0];
    const float* mask = (const float*)d_in[1];
    const float* Wq   = (const float*)d_in[2];
    const float* bq   = (const float*)d_in[3];
    const float* Wh   = (const float*)d_in[4];
    const float* bh   = (const float*)d_in[5];
    const float* Ws   = (const float*)d_in[6];
    const float* bs   = (const float*)d_in[7];
    float* out = (float*)d_out;

    k1_qproj<<<dim3(2, 128), 256>>>(X, Wq, bq);
    ksq<<<8192, 256>>>();
    k2a_h<<<dim3(1, 128), 256>>>(X, Wh, bh);
    k2b_sin<<<dim3(4, 128), 256>>>(Ws, bs);
    k3_logits<<<dim3(8, 8, 16), 256>>>(mask);
    k3b_rowsum<<<2048, 256>>>();
    k4_pv<<<dim3(4, 8, 16), 256>>>(out);
    k5_tq<<<16, 256>>>(out + (size_t)BB * LL * YD);
}

// round 5
// speedup vs baseline: 2.4313x; 1.4857x over previous
#include <cuda_runtime.h>
#include <cstdint>

#define LL 1024
#define BB 16
#define XD 512
#define YD 512
#define QDIM 64
#define ND 4
#define HL 128
#define RSQRT512 0.04419417382415922f

#define BK 16
#define ALD 20            // padded [row][k] stride
#define BLDF 136          // padded [k][n] stride for non-transposed B
#define A_STAGE (128*ALD)
#define BT_STAGE (128*ALD)
#define BN_STAGE (16*BLDF)

// -------- scratch (device globals; no allocation allowed) --------
__device__ float g_Q  [ND*BB*LL*QDIM];        // [d][b][l][q]
__device__ float g_sq [ND*BB*LL];             // [d][b][l]
__device__ float g_h  [BB*LL*HL];             // [m][h]
__device__ float g_Sin[BB*LL*YD];             // [b][l][y]
__device__ float g_E  [(size_t)BB*LL*LL];     // [b][i][j]
__device__ float g_R  [BB*LL];                // rowsums (atomic-accumulated)
__device__ float g_TQp[BB*8*QDIM];            // k5 partials

__device__ __forceinline__ void cp16(float* dst, const float* src) {
    uint32_t d = (uint32_t)__cvta_generic_to_shared(dst);
    asm volatile("cp.async.cg.shared.global [%0], [%1], 16;" :: "r"(d), "l"(src));
}
#define CP_COMMIT asm volatile("cp.async.commit_group;")
#define CP_WAIT0  asm volatile("cp.async.wait_group 0;")

__device__ __forceinline__ uint32_t f2tf(float f) {
    uint32_t r; asm("cvt.rna.tf32.f32 %0, %1;" : "=r"(r) : "f"(f)); return r;
}

__device__ __forceinline__ void mma_tf32(float c[4], const uint32_t a[4], const uint32_t b[2]) {
    asm volatile("mma.sync.aligned.m16n8k8.row.col.f32.tf32.tf32.f32 "
        "{%0,%1,%2,%3}, {%4,%5,%6,%7}, {%8,%9}, {%0,%1,%2,%3};"
        : "+f"(c[0]), "+f"(c[1]), "+f"(c[2]), "+f"(c[3])
        : "r"(a[0]), "r"(a[1]), "r"(a[2]), "r"(a[3]), "r"(b[0]), "r"(b[1]));
}

// ---------------- pipelined 128x128 tf32 GEMM mainloop ----------------
//  BT=true : Bg is [N][K] row-major (weights)      -> smem [n][k] (ALD)
//  BT=false: Bg is [K][N] row-major (activations)  -> smem [k][n] (BLDF)
template<bool BT>
__device__ __forceinline__ void gemm_pipe(const float* __restrict__ A, int lda,
                                          const float* __restrict__ Bg, int ldb,
                                          int K, float acc[2][8][4],
                                          float* As, float* Bs)
{
    const int tid = threadIdx.x;
    const int lane = tid & 31, warp = tid >> 5;
    const int wm = (warp & 3) * 32, wn = (warp >> 2) * 64;
    const int qr = lane >> 2, qc = lane & 3;
    const int NIT = K / BK;

    const int r2  = (tid*2) >> 2, k42 = ((tid*2) & 3) * 4;
    const int r2b = (tid*2+1) >> 2, k42b = ((tid*2+1) & 3) * 4;
    const int nk  = (tid*2) >> 5, n4  = ((tid*2) & 31) * 4;
    const int nkb = (tid*2+1) >> 5, n4b = ((tid*2+1) & 31) * 4;

    #define ISSUE(s, k0)  do {                                                      \
        cp16(&As[(s)*A_STAGE + r2 *ALD + k42 ], A + (size_t)r2 *lda + (k0) + k42 ); \
        cp16(&As[(s)*A_STAGE + r2b*ALD + k42b], A + (size_t)r2b*lda + (k0) + k42b); \
        if (BT) {                                                                   \
            cp16(&Bs[(s)*BT_STAGE + r2 *ALD + k42 ], Bg + (size_t)r2 *ldb + (k0) + k42 ); \
            cp16(&Bs[(s)*BT_STAGE + r2b*ALD + k42b], Bg + (size_t)r2b*ldb + (k0) + k42b); \
        } else {                                                                    \
            cp16(&Bs[(s)*BN_STAGE + nk *BLDF + n4 ], Bg + (size_t)((k0)+nk )*ldb + n4 );  \
            cp16(&Bs[(s)*BN_STAGE + nkb*BLDF + n4b], Bg + (size_t)((k0)+nkb)*ldb + n4b);  \
        }                                                                           \
        CP_COMMIT;                                                                  \
    } while (0)

    ISSUE(0, 0);
    for (int it = 0; it < NIT; ++it) {
        CP_WAIT0;
        __syncthreads();
        if (it + 1 < NIT) ISSUE((it+1)&1, (it+1)*BK);
        const float* as = As + (it&1)*A_STAGE;
        const float* bs = Bs + (it&1)*(BT ? BT_STAGE : BN_STAGE);
        #pragma unroll
        for (int kk = 0; kk < 2; kk++) {
            uint32_t af[2][4];
            #pragma unroll
            for (int m = 0; m < 2; m++) {
                int r = wm + m*16 + qr, c = kk*8 + qc;
                af[m][0] = f2tf(as[r*ALD + c]);
                af[m][1] = f2tf(as[(r+8)*ALD + c]);
                af[m][2] = f2tf(as[r*ALD + c + 4]);
                af[m][3] = f2tf(as[(r+8)*ALD + c + 4]);
            }
            uint32_t bf[8][2];
            #pragma unroll
            for (int n = 0; n < 8; n++) {
                int cn = wn + n*8 + qr, rk = kk*8 + qc;
                if (BT) { bf[n][0] = f2tf(bs[cn*ALD + rk]);
                          bf[n][1] = f2tf(bs[cn*ALD + rk + 4]); }
                else    { bf[n][0] = f2tf(bs[rk*BLDF + cn]);
                          bf[n][1] = f2tf(bs[(rk+4)*BLDF + cn]); }
            }
            #pragma unroll
            for (int m = 0; m < 2; m++)
                #pragma unroll
                for (int n = 0; n < 8; n++)
                    mma_tf32(acc[m][n], af[m], bf[n]);
        }
    }
    #undef ISSUE
}

// ============================================================
// K1: Qins = X @ Wq^T + bq  -> g_Q[d][b][l][q], fused sq reduction
// ============================================================
__global__ __launch_bounds__(256, 2) void k1_qproj(const float* __restrict__ X,
                                                   const float* __restrict__ Wq,
                                                   const float* __restrict__ bq) {
    __shared__ float As[2*A_STAGE], Bs[2*BT_STAGE];
    const int row0 = blockIdx.y * 128, col0 = blockIdx.x * 128;
    float acc[2][8][4] = {};
    gemm_pipe<true>(X + (size_t)row0 * XD, XD, Wq + (size_t)col0 * XD, XD, XD, acc, As, Bs);
    const int lane = threadIdx.x & 31, warp = threadIdx.x >> 5;
    const int wm = (warp & 3) * 32, wn = (warp >> 2) * 64;
    const int qr = lane >> 2, qc = lane & 3;
    const int d = (col0 + wn) >> 6;
    #pragma unroll
    for (int m = 0; m < 2; m++)
        #pragma unroll
        for (int rr = 0; rr < 2; rr++) {
            int mrow = row0 + wm + m*16 + qr + rr*8;
            int l = mrow >> 4, b = mrow & 15;
            float s = 0.f;
            #pragma unroll
            for (int n = 0; n < 8; n++) {
                int cg = col0 + wn + n*8 + 2*qc;
                int q = cg & 63;
                float2 v;
                v.x = acc[m][n][rr*2+0] + bq[cg];
                v.y = acc[m][n][rr*2+1] + bq[cg+1];
                s += v.x*v.x + v.y*v.y;
                *(float2*)&g_Q[(((size_t)d*BB + b)*LL + l)*QDIM + q] = v;
            }
            s += __shfl_xor_sync(0xffffffffu, s, 1);
            s += __shfl_xor_sync(0xffffffffu, s, 2);
            if (qc == 0) g_sq[((size_t)d*BB + b)*LL + l] = s;
        }
}

// ============================================================
// kzero: clear g_R
// ============================================================
__global__ void kzero() {
    int i = blockIdx.x * 256 + threadIdx.x;
    if (i < BB*LL) g_R[i] = 0.f;
}

// ============================================================
// K2a: h = sigmoid(X @ Wh^T + bh)
// ============================================================
__global__ __launch_bounds__(256, 2) void k2a_h(const float* __restrict__ X,
                                                const float* __restrict__ Wh,
                                                const float* __restrict__ bh) {
    __shared__ float As[2*A_STAGE], Bs[2*BT_STAGE];
    const int row0 = blockIdx.y * 128;
    float acc[2][8][4] = {};
    gemm_pipe<true>(X + (size_t)row0 * XD, XD, Wh, XD, XD, acc, As, Bs);
    const int lane = threadIdx.x & 31, warp = threadIdx.x >> 5;
    const int wm = (warp & 3) * 32, wn = (warp >> 2) * 64;
    const int qr = lane >> 2, qc = lane & 3;
    #pragma unroll
    for (int m = 0; m < 2; m++)
        #pragma unroll
        for (int rr = 0; rr < 2; rr++) {
            int mrow = row0 + wm + m*16 + qr + rr*8;
            #pragma unroll
            for (int n = 0; n < 8; n++) {
                int cg = wn + n*8 + 2*qc;
                float2 v;
                v.x = 1.f / (1.f + __expf(-(acc[m][n][rr*2+0] + bh[cg])));
                v.y = 1.f / (1.f + __expf(-(acc[m][n][rr*2+1] + bh[cg+1])));
                *(float2*)&g_h[(size_t)mrow * HL + cg] = v;
            }
        }
}

// ============================================================
// K2b: Sin = h @ Ws^T + bs -> g_Sin[b][l][y]
// ============================================================
__global__ __launch_bounds__(256, 2) void k2b_sin(const float* __restrict__ Ws,
                                                  const float* __restrict__ bs) {
    __shared__ float As[2*A_STAGE], Bs[2*BT_STAGE];
    const int row0 = blockIdx.y * 128, col0 = blockIdx.x * 128;
    float acc[2][8][4] = {};
    gemm_pipe<true>(g_h + (size_t)row0 * HL, HL, Ws + (size_t)col0 * HL, HL, HL, acc, As, Bs);
    const int lane = threadIdx.x & 31, warp = threadIdx.x >> 5;
    const int wm = (warp & 3) * 32, wn = (warp >> 2) * 64;
    const int qr = lane >> 2, qc = lane & 3;
    #pragma unroll
    for (int m = 0; m < 2; m++)
        #pragma unroll
        for (int rr = 0; rr < 2; rr++) {
            int mrow = row0 + wm + m*16 + qr + rr*8;
            int l = mrow >> 4, b = mrow & 15;
            #pragma unroll
            for (int n = 0; n < 8; n++) {
                int cg = col0 + wn + n*8 + 2*qc;
                float2 v;
                v.x = acc[m][n][rr*2+0] + bs[cg];
                v.y = acc[m][n][rr*2+1] + bs[cg+1];
                *(float2*)&g_Sin[((size_t)b*LL + l)*YD + cg] = v;
            }
        }
}

// ============================================================
// K3: fused pairwise-distance logits -> E, fused rowsum atomics
// 128x64 tiles, flattened 16-iter pipeline across 4 d's
// ============================================================
#define K3_BSTAGE (64*ALD)
__global__ __launch_bounds__(256, 2) void k3_logits(const float* __restrict__ mask) {
    __shared__ float As[2*A_STAGE], Bs[2*K3_BSTAGE];
    const int bI = blockIdx.z;
    const int i0 = blockIdx.y * 128, j0 = blockIdx.x * 64;
    const int tid = threadIdx.x;
    const int lane = tid & 31, warp = tid >> 5;
    const int wm = (warp & 3) * 32, wn = (warp >> 2) * 32;
    const int qr = lane >> 2, qc = lane & 3;

    const int r2  = (tid*2) >> 2, k42 = ((tid*2) & 3) * 4;
    const int r2b = (tid*2+1) >> 2, k42b = ((tid*2+1) & 3) * 4;
    const int bn  = tid >> 2, bk4 = (tid & 3) * 4;

    #define K3_ISSUE(s, t) do {                                                     \
        int d_ = (t) >> 2, ko_ = ((t) & 3) * BK;                                    \
        const float* Ab_ = g_Q + (((size_t)d_*BB + bI)*LL + i0) * QDIM + ko_;       \
        const float* Bb_ = g_Q + (((size_t)d_*BB + bI)*LL + j0) * QDIM + ko_;       \
        cp16(&As[(s)*A_STAGE + r2 *ALD + k42 ], Ab_ + (size_t)r2 *QDIM + k42 );     \
        cp16(&As[(s)*A_STAGE + r2b*ALD + k42b], Ab_ + (size_t)r2b*QDIM + k42b);     \
        cp16(&Bs[(s)*K3_BSTAGE + bn*ALD + bk4], Bb_ + (size_t)bn*QDIM + bk4);       \
        CP_COMMIT;                                                                  \
    } while (0)

    float logit[2][4][4] = {};
    float acc[2][4][4] = {};
    K3_ISSUE(0, 0);
    for (int t = 0; t < 16; ++t) {
        CP_WAIT0;
        __syncthreads();
        if (t + 1 < 16) K3_ISSUE((t+1)&1, t+1);
        const float* as = As + (t&1)*A_STAGE;
        const float* bs = Bs + (t&1)*K3_BSTAGE;
        #pragma unroll
        for (int kk = 0; kk < 2; kk++) {
            uint32_t af[2][4];
            #pragma unroll
            for (int m = 0; m < 2; m++) {
                int r = wm + m*16 + qr, c = kk*8 + qc;
                af[m][0] = f2tf(as[r*ALD + c]);
                af[m][1] = f2tf(as[(r+8)*ALD + c]);
                af[m][2] = f2tf(as[r*ALD + c + 4]);
                af[m][3] = f2tf(as[(r+8)*ALD + c + 4]);
            }
            uint32_t bf[4][2];
            #pragma unroll
            for (int n = 0; n < 4; n++) {
                int cn = wn + n*8 + qr, rk = kk*8 + qc;
                bf[n][0] = f2tf(bs[cn*ALD + rk]);
                bf[n][1] = f2tf(bs[cn*ALD + rk + 4]);
            }
            #pragma unroll
            for (int m = 0; m < 2; m++)
                #pragma unroll
                for (int n = 0; n < 4; n++)
                    mma_tf32(acc[m][n], af[m], bf[n]);
        }
        if ((t & 3) == 3) {
            const int d = t >> 2;
            const float sgn = (d & 1) ? -1.f : 1.f;
            const float* sqb = g_sq + ((size_t)d*BB + bI) * LL;
            #pragma unroll
            for (int m = 0; m < 2; m++)
                #pragma unroll
                for (int rr = 0; rr < 2; rr++) {
                    int gi = i0 + wm + m*16 + qr + rr*8;
                    float sqi = sqb[gi];
                    #pragma unroll
                    for (int n = 0; n < 4; n++) {
                        int gj = j0 + wn + n*8 + 2*qc;
                        float d20 = fmaxf(sqi + sqb[gj]   - 2.f*acc[m][n][rr*2+0], 0.f);
                        float d21 = fmaxf(sqi + sqb[gj+1] - 2.f*acc[m][n][rr*2+1], 0.f);
                        logit[m][n][rr*2+0] += (gi == gj)   ? 0.f : sgn * sqrtf(d20);
                        logit[m][n][rr*2+1] += (gi == gj+1) ? 0.f : sgn * sqrtf(d21);
                        acc[m][n][rr*2+0] = 0.f;
                        acc[m][n][rr*2+1] = 0.f;
                    }
                }
        }
    }
    #undef K3_ISSUE
    #pragma unroll
    for (int m = 0; m < 2; m++)
        #pragma unroll
        for (int rr = 0; rr < 2; rr++) {
            int gi = i0 + wm + m*16 + qr + rr*8;
            float s = 0.f;
            #pragma unroll
            for (int n = 0; n < 4; n++) {
                int gj = j0 + wn + n*8 + 2*qc;
                float2 mv = *(const float2*)&mask[(size_t)gi * LL + gj];
                float2 e;
                e.x = __expf(logit[m][n][rr*2+0] * RSQRT512 + mv.x);
                e.y = __expf(logit[m][n][rr*2+1] * RSQRT512 + mv.y);
                s += e.x + e.y;
                *(float2*)&g_E[((size_t)bI*LL + gi)*LL + gj] = e;
            }
            s += __shfl_xor_sync(0xffffffffu, s, 1);
            s += __shfl_xor_sync(0xffffffffu, s, 2);
            if (qc == 0) atomicAdd(&g_R[bI*LL + gi], s);
        }
}

// ============================================================
// K4: Sout[b] = diag(1/R) * E[b] @ Sin[b]
// ============================================================
__global__ __launch_bounds__(256, 2) void k4_pv(float* __restrict__ out) {
    __shared__ float As[2*A_STAGE], Bs[2*BN_STAGE];
    const int b = blockIdx.z;
    const int row0 = blockIdx.y * 128, col0 = blockIdx.x * 128;
    float acc[2][8][4] = {};
    gemm_pipe<false>(g_E + (size_t)b*LL*LL + (size_t)row0 * LL, LL,
                     g_Sin + (size_t)b*LL*YD + col0, YD, LL, acc, As, Bs);
    const int lane = threadIdx.x & 31, warp = threadIdx.x >> 5;
    const int wm = (warp & 3) * 32, wn = (warp >> 2) * 64;
    const int qr = lane >> 2, qc = lane & 3;
    #pragma unroll
    for (int m = 0; m < 2; m++)
        #pragma unroll
        for (int rr = 0; rr < 2; rr++) {
            int row = row0 + wm + m*16 + qr + rr*8;
            float rinv = 1.f / g_R[b*LL + row];
            #pragma unroll
            for (int n = 0; n < 8; n++) {
                int col = col0 + wn + n*8 + 2*qc;
                float2 v;
                v.x = acc[m][n][rr*2+0] * rinv;
                v.y = acc[m][n][rr*2+1] * rinv;
                *(float2*)&out[((size_t)b*LL + row)*YD + col] = v;
            }
        }
}

// ============================================================
// K5a/K5b: temp_Qins two-stage mean
// ============================================================
__global__ __launch_bounds__(256) void k5a() {
    const int b = blockIdx.x, lc = blockIdx.y;
    const int t = threadIdx.x;
    const int q = t & 63, part = t >> 6;
    float s = 0.f;
    #pragma unroll
    for (int d = 0; d < ND; d++) {
        const float* base = g_Q + (((size_t)d*BB + b)*LL + lc*128) * QDIM;
        for (int l = part; l < 128; l += 4) s += base[(size_t)l * QDIM + q];
    }
    __shared__ float red[256];
    red[t] = s;
    __syncthreads();
    if (part == 0)
        g_TQp[(b*8 + lc)*QDIM + q] = red[q] + red[64+q] + red[128+q] + red[192+q];
}
__global__ void k5b(float* __restrict__ out2) {
    const int b = blockIdx.x, q = threadIdx.x;
    float s = 0.f;
    #pragma unroll
    for (int lc = 0; lc < 8; lc++) s += g_TQp[(b*8 + lc)*QDIM + q];
    out2[b*QDIM + q] = s * (1.f / (ND * (float)LL));
}

// ============================================================
extern "C" void kernel_launch(void* const* d_in, const int* in_sizes, int n_in,
                              void* d_out, int out_size) {
    const float* X    = (const float*)d_in[0];
    const float* mask = (const float*)d_in[1];
    const float* Wq   = (const float*)d_in[2];
    const float* bq   = (const float*)d_in[3];
    const float* Wh   = (const float*)d_in[4];
    const float* bh   = (const float*)d_in[5];
    const float* Ws   = (const float*)d_in[6];
    const float* bs   = (const float*)d_in[7];
    float* out = (float*)d_out;

    k1_qproj<<<dim3(2, 128), 256>>>(X, Wq, bq);
    kzero<<<64, 256>>>();
    k2a_h<<<dim3(1, 128), 256>>>(X, Wh, bh);
    k2b_sin<<<dim3(4, 128), 256>>>(Ws, bs);
    k3_logits<<<dim3(16, 8, 16), 256>>>(mask);
    k4_pv<<<dim3(4, 8, 16), 256>>>(out);
    k5a<<<dim3(16, 8), 256>>>();
    k5b<<<16, 64>>>(out + (size_t)BB * LL * YD);
}

// round 6
// speedup vs baseline: 2.4752x; 1.0181x over previous
#include <cuda_runtime.h>
#include <cstdint>

#define LL 1024
#define BB 16
#define XD 512
#define YD 512
#define QDIM 64
#define ND 4
#define HL 128
#define MTOT (LL*BB)
#define RSQRT512 0.04419417382415922f

#define BK 16
#define ALD 20                    // padded [row][k] float stride (16B-aligned rows, conflict-free)
#define A_STAGE (128*ALD)
#define K3_BSTAGE (64*ALD)

// -------- scratch (device globals; no allocation allowed) --------
__device__ float g_X  [MTOT*XD];              // tf32-rounded X
__device__ float g_Wq [ND*QDIM*XD];           // tf32-rounded Wq
__device__ float g_Wh [HL*XD];                // tf32-rounded Wh
__device__ float g_Ws [YD*HL];                // tf32-rounded Ws
__device__ float g_Q  [ND*BB*LL*QDIM];        // [d][b][l][q] (rounded)
__device__ float g_sq [ND*BB*LL];
__device__ float g_h  [MTOT*HL];              // (rounded)
__device__ float g_SinT[(size_t)BB*YD*LL];    // [b][y][l] (rounded)
__device__ float g_E  [(size_t)BB*LL*LL];     // [b][i][j] (rounded)
__device__ float g_R  [BB*LL];
__device__ float g_TQp[BB*8*QDIM];

__device__ __forceinline__ void cp16(float* dst, const float* src) {
    uint32_t d = (uint32_t)__cvta_generic_to_shared(dst);
    asm volatile("cp.async.cg.shared.global [%0], [%1], 16;" :: "r"(d), "l"(src));
}
#define CP_COMMIT asm volatile("cp.async.commit_group;")
#define CP_WAIT0  asm volatile("cp.async.wait_group 0;")
#define CP_WAIT1  asm volatile("cp.async.wait_group 1;")

__device__ __forceinline__ uint32_t f2tf(float f) {
    uint32_t r; asm("cvt.rna.tf32.f32 %0, %1;" : "=r"(r) : "f"(f)); return r;
}
__device__ __forceinline__ float rtf(float f) { return __uint_as_float(f2tf(f)); }

__device__ __forceinline__ void ldsm4(uint32_t r[4], uint32_t addr) {
    asm volatile("ldmatrix.sync.aligned.m8n8.x4.shared.b16 {%0,%1,%2,%3}, [%4];"
        : "=r"(r[0]), "=r"(r[1]), "=r"(r[2]), "=r"(r[3]) : "r"(addr));
}
__device__ __forceinline__ void mma_tf32(float c[4], const uint32_t a[4],
                                         uint32_t b0, uint32_t b1) {
    asm volatile("mma.sync.aligned.m16n8k8.row.col.f32.tf32.tf32.f32 "
        "{%0,%1,%2,%3}, {%4,%5,%6,%7}, {%8,%9}, {%0,%1,%2,%3};"
        : "+f"(c[0]), "+f"(c[1]), "+f"(c[2]), "+f"(c[3])
        : "r"(a[0]), "r"(a[1]), "r"(a[2]), "r"(a[3]), "r"(b0), "r"(b1));
}

// ---------------- 3-stage pipelined 128x128 tf32 GEMM, BT form + ldmatrix ----
// A: [M=128 rows][K] row-major (lda). Bg: [N=128 rows][K] row-major (ldb).
// Data must be tf32-pre-rounded. Warp tile 32x64.
template<int NIT>
__device__ __forceinline__ void gemm_bt(const float* __restrict__ A, int lda,
                                        const float* __restrict__ Bg, int ldb,
                                        float acc[2][8][4], float* As, float* Bs)
{
    const int tid = threadIdx.x;
    const int lane = tid & 31, warp = tid >> 5;
    const int wm = (warp & 3) * 32, wn = (warp >> 2) * 64;
    const int r2  = (tid*2) >> 2,   k42  = ((tid*2)   & 3) * 4;
    const int r2b = (tid*2+1) >> 2, k42b = ((tid*2+1) & 3) * 4;
    const uint32_t aSm = (uint32_t)__cvta_generic_to_shared(As);
    const uint32_t bSm = (uint32_t)__cvta_generic_to_shared(Bs);
    uint32_t offA[2], offB[4];
    #pragma unroll
    for (int m = 0; m < 2; m++)
        offA[m] = ((wm + m*16 + (lane & 15))*ALD + ((lane & 16) >> 2)) * 4;
    #pragma unroll
    for (int p = 0; p < 4; p++)
        offB[p] = ((wn + p*16 + (lane & 7) + ((lane & 16) >> 1))*ALD + ((lane & 8) >> 1)) * 4;

    #define ISSUE(s, k0) do {                                                        \
        cp16(&As[(s)*A_STAGE + r2 *ALD + k42 ], A  + (size_t)r2 *lda + (k0) + k42 ); \
        cp16(&As[(s)*A_STAGE + r2b*ALD + k42b], A  + (size_t)r2b*lda + (k0) + k42b); \
        cp16(&Bs[(s)*A_STAGE + r2 *ALD + k42 ], Bg + (size_t)r2 *ldb + (k0) + k42 ); \
        cp16(&Bs[(s)*A_STAGE + r2b*ALD + k42b], Bg + (size_t)r2b*ldb + (k0) + k42b); \
        CP_COMMIT;                                                                   \
    } while (0)

    ISSUE(0, 0);
    ISSUE(1, BK);
    for (int it = 0; it < NIT; ++it) {
        if (it + 1 < NIT) { CP_WAIT1; } else { CP_WAIT0; }
        __syncthreads();
        if (it + 2 < NIT) ISSUE((it + 2) % 3, (it + 2) * BK);
        const uint32_t aB = aSm + (it % 3) * (A_STAGE * 4);
        const uint32_t bB = bSm + (it % 3) * (A_STAGE * 4);
        #pragma unroll
        for (int kk = 0; kk < 2; kk++) {
            uint32_t af[2][4];
            ldsm4(af[0], aB + offA[0] + kk*32);
            ldsm4(af[1], aB + offA[1] + kk*32);
            uint32_t bf[4][4];
            #pragma unroll
            for (int p = 0; p < 4; p++) ldsm4(bf[p], bB + offB[p] + kk*32);
            #pragma unroll
            for (int m = 0; m < 2; m++)
                #pragma unroll
                for (int n = 0; n < 8; n++)
                    mma_tf32(acc[m][n], af[m], bf[n>>1][(n&1)*2], bf[n>>1][(n&1)*2+1]);
        }
    }
    #undef ISSUE
}

// ============================================================
// kround: tf32-round a tensor (n multiple of 4)
// ============================================================
__global__ void kround(const float* __restrict__ src, float* __restrict__ dst, int n) {
    int i = (blockIdx.x * 256 + threadIdx.x) * 4;
    if (i < n) {
        float4 v = *(const float4*)(src + i);
        v.x = rtf(v.x); v.y = rtf(v.y); v.z = rtf(v.z); v.w = rtf(v.w);
        *(float4*)(dst + i) = v;
    }
}

// ============================================================
// K1: Qins = X @ Wq^T + bq -> g_Q (rounded), fused sq
// ============================================================
__global__ __launch_bounds__(256, 2) void k1_qproj(const float* __restrict__ bq) {
    __shared__ float As[3*A_STAGE], Bs[3*A_STAGE];
    const int row0 = blockIdx.y * 128, col0 = blockIdx.x * 128;
    float acc[2][8][4] = {};
    gemm_bt<XD/BK>(g_X + (size_t)row0 * XD, XD, g_Wq + (size_t)col0 * XD, XD, acc, As, Bs);
    const int lane = threadIdx.x & 31, warp = threadIdx.x >> 5;
    const int wm = (warp & 3) * 32, wn = (warp >> 2) * 64;
    const int qr = lane >> 2, qc = lane & 3;
    const int d = (col0 + wn) >> 6;
    #pragma unroll
    for (int m = 0; m < 2; m++)
        #pragma unroll
        for (int rr = 0; rr < 2; rr++) {
            int mrow = row0 + wm + m*16 + qr + rr*8;
            int l = mrow >> 4, b = mrow & 15;
            float s = 0.f;
            #pragma unroll
            for (int n = 0; n < 8; n++) {
                int cg = col0 + wn + n*8 + 2*qc;
                int q = cg & 63;
                float2 v;
                v.x = rtf(acc[m][n][rr*2+0] + bq[cg]);
                v.y = rtf(acc[m][n][rr*2+1] + bq[cg+1]);
                s += v.x*v.x + v.y*v.y;
                *(float2*)&g_Q[(((size_t)d*BB + b)*LL + l)*QDIM + q] = v;
            }
            s += __shfl_xor_sync(0xffffffffu, s, 1);
            s += __shfl_xor_sync(0xffffffffu, s, 2);
            if (qc == 0) g_sq[((size_t)d*BB + b)*LL + l] = s;
        }
}

// ============================================================
__global__ void kzero() {
    int i = blockIdx.x * 256 + threadIdx.x;
    if (i < BB*LL) g_R[i] = 0.f;
}

// ============================================================
// K2a: h = sigmoid(X @ Wh^T + bh)  (rounded)
// ============================================================
__global__ __launch_bounds__(256, 2) void k2a_h(const float* __restrict__ bh) {
    __shared__ float As[3*A_STAGE], Bs[3*A_STAGE];
    const int row0 = blockIdx.y * 128;
    float acc[2][8][4] = {};
    gemm_bt<XD/BK>(g_X + (size_t)row0 * XD, XD, g_Wh, XD, acc, As, Bs);
    const int lane = threadIdx.x & 31, warp = threadIdx.x >> 5;
    const int wm = (warp & 3) * 32, wn = (warp >> 2) * 64;
    const int qr = lane >> 2, qc = lane & 3;
    #pragma unroll
    for (int m = 0; m < 2; m++)
        #pragma unroll
        for (int rr = 0; rr < 2; rr++) {
            int mrow = row0 + wm + m*16 + qr + rr*8;
            #pragma unroll
            for (int n = 0; n < 8; n++) {
                int cg = wn + n*8 + 2*qc;
                float2 v;
                v.x = rtf(1.f / (1.f + __expf(-(acc[m][n][rr*2+0] + bh[cg]))));
                v.y = rtf(1.f / (1.f + __expf(-(acc[m][n][rr*2+1] + bh[cg+1]))));
                *(float2*)&g_h[(size_t)mrow * HL + cg] = v;
            }
        }
}

// ============================================================
// K2b: Sin = h @ Ws^T + bs -> g_SinT[b][y][l]  (rounded, transposed)
// ============================================================
__global__ __launch_bounds__(256, 2) void k2b_sin(const float* __restrict__ bs) {
    __shared__ float As[3*A_STAGE], Bs[3*A_STAGE];
    const int row0 = blockIdx.y * 128, col0 = blockIdx.x * 128;
    float acc[2][8][4] = {};
    gemm_bt<HL/BK>(g_h + (size_t)row0 * HL, HL, g_Ws + (size_t)col0 * HL, HL, acc, As, Bs);
    const int lane = threadIdx.x & 31, warp = threadIdx.x >> 5;
    const int wm = (warp & 3) * 32, wn = (warp >> 2) * 64;
    const int qr = lane >> 2, qc = lane & 3;
    #pragma unroll
    for (int m = 0; m < 2; m++)
        #pragma unroll
        for (int rr = 0; rr < 2; rr++) {
            int mrow = row0 + wm + m*16 + qr + rr*8;
            int l = mrow >> 4, b = mrow & 15;
            #pragma unroll
            for (int n = 0; n < 8; n++) {
                int cg = col0 + wn + n*8 + 2*qc;   // y, y+1
                float v0 = rtf(acc[m][n][rr*2+0] + bs[cg]);
                float v1 = rtf(acc[m][n][rr*2+1] + bs[cg+1]);
                g_SinT[((size_t)b*YD + cg  )*LL + l] = v0;
                g_SinT[((size_t)b*YD + cg+1)*LL + l] = v1;
            }
        }
}

// ============================================================
// K3: fused pairwise-distance logits -> E (rounded), fused rowsum
// 128x64 tiles; 16 pipelined iters across 4 d's
// ============================================================
__global__ __launch_bounds__(256, 2) void k3_logits(const float* __restrict__ mask) {
    __shared__ float As[3*A_STAGE], Bs[3*K3_BSTAGE];
    const int bI = blockIdx.z;
    const int i0 = blockIdx.y * 128, j0 = blockIdx.x * 64;
    const int tid = threadIdx.x;
    const int lane = tid & 31, warp = tid >> 5;
    const int wm = (warp & 3) * 32, wn = (warp >> 2) * 32;
    const int qr = lane >> 2, qc = lane & 3;

    const int r2  = (tid*2) >> 2,   k42  = ((tid*2)   & 3) * 4;
    const int r2b = (tid*2+1) >> 2, k42b = ((tid*2+1) & 3) * 4;
    const int bn  = tid >> 2, bk4 = (tid & 3) * 4;

    const uint32_t aSm = (uint32_t)__cvta_generic_to_shared(As);
    const uint32_t bSm = (uint32_t)__cvta_generic_to_shared(Bs);
    uint32_t offA[2], offB[2];
    #pragma unroll
    for (int m = 0; m < 2; m++)
        offA[m] = ((wm + m*16 + (lane & 15))*ALD + ((lane & 16) >> 2)) * 4;
    #pragma unroll
    for (int p = 0; p < 2; p++)
        offB[p] = ((wn + p*16 + (lane & 7) + ((lane & 16) >> 1))*ALD + ((lane & 8) >> 1)) * 4;

    #define K3_ISSUE(s, t) do {                                                     \
        int d_ = (t) >> 2, ko_ = ((t) & 3) * BK;                                    \
        const float* Ab_ = g_Q + (((size_t)d_*BB + bI)*LL + i0) * QDIM + ko_;       \
        const float* Bb_ = g_Q + (((size_t)d_*BB + bI)*LL + j0) * QDIM + ko_;       \
        cp16(&As[(s)*A_STAGE + r2 *ALD + k42 ], Ab_ + (size_t)r2 *QDIM + k42 );     \
        cp16(&As[(s)*A_STAGE + r2b*ALD + k42b], Ab_ + (size_t)r2b*QDIM + k42b);     \
        cp16(&Bs[(s)*K3_BSTAGE + bn*ALD + bk4], Bb_ + (size_t)bn*QDIM + bk4);       \
        CP_COMMIT;                                                                  \
    } while (0)

    float logit[2][4][4] = {};
    float acc[2][4][4] = {};
    K3_ISSUE(0, 0);
    K3_ISSUE(1, 1);
    for (int t = 0; t < 16; ++t) {
        if (t + 1 < 16) { CP_WAIT1; } else { CP_WAIT0; }
        __syncthreads();
        if (t + 2 < 16) K3_ISSUE((t + 2) % 3, t + 2);
        const uint32_t aB = aSm + (t % 3) * (A_STAGE * 4);
        const uint32_t bB = bSm + (t % 3) * (K3_BSTAGE * 4);
        #pragma unroll
        for (int kk = 0; kk < 2; kk++) {
            uint32_t af[2][4];
            ldsm4(af[0], aB + offA[0] + kk*32);
            ldsm4(af[1], aB + offA[1] + kk*32);
            uint32_t bf[2][4];
            ldsm4(bf[0], bB + offB[0] + kk*32);
            ldsm4(bf[1], bB + offB[1] + kk*32);
            #pragma unroll
            for (int m = 0; m < 2; m++)
                #pragma unroll
                for (int n = 0; n < 4; n++)
                    mma_tf32(acc[m][n], af[m], bf[n>>1][(n&1)*2], bf[n>>1][(n&1)*2+1]);
        }
        if ((t & 3) == 3) {
            const int d = t >> 2;
            const float sgn = (d & 1) ? -1.f : 1.f;
            const float* sqb = g_sq + ((size_t)d*BB + bI) * LL;
            #pragma unroll
            for (int m = 0; m < 2; m++)
                #pragma unroll
                for (int rr = 0; rr < 2; rr++) {
                    int gi = i0 + wm + m*16 + qr + rr*8;
                    float sqi = sqb[gi];
                    #pragma unroll
                    for (int n = 0; n < 4; n++) {
                        int gj = j0 + wn + n*8 + 2*qc;
                        float d20 = fmaxf(sqi + sqb[gj]   - 2.f*acc[m][n][rr*2+0], 0.f);
                        float d21 = fmaxf(sqi + sqb[gj+1] - 2.f*acc[m][n][rr*2+1], 0.f);
                        logit[m][n][rr*2+0] += (gi == gj)   ? 0.f : sgn * sqrtf(d20);
                        logit[m][n][rr*2+1] += (gi == gj+1) ? 0.f : sgn * sqrtf(d21);
                        acc[m][n][rr*2+0] = 0.f;
                        acc[m][n][rr*2+1] = 0.f;
                    }
                }
        }
    }
    #undef K3_ISSUE
    #pragma unroll
    for (int m = 0; m < 2; m++)
        #pragma unroll
        for (int rr = 0; rr < 2; rr++) {
            int gi = i0 + wm + m*16 + qr + rr*8;
            float s = 0.f;
            #pragma unroll
            for (int n = 0; n < 4; n++) {
                int gj = j0 + wn + n*8 + 2*qc;
                float2 mv = *(const float2*)&mask[(size_t)gi * LL + gj];
                float2 e;
                e.x = rtf(__expf(logit[m][n][rr*2+0] * RSQRT512 + mv.x));
                e.y = rtf(__expf(logit[m][n][rr*2+1] * RSQRT512 + mv.y));
                s += e.x + e.y;
                *(float2*)&g_E[((size_t)bI*LL + gi)*LL + gj] = e;
            }
            s += __shfl_xor_sync(0xffffffffu, s, 1);
            s += __shfl_xor_sync(0xffffffffu, s, 2);
            if (qc == 0) atomicAdd(&g_R[bI*LL + gi], s);
        }
}

// ============================================================
// K4: Sout[b] = diag(1/R) * E[b] @ SinT[b]^T
// ============================================================
__global__ __launch_bounds__(256, 2) void k4_pv(float* __restrict__ out) {
    __shared__ float As[3*A_STAGE], Bs[3*A_STAGE];
    const int b = blockIdx.z;
    const int row0 = blockIdx.y * 128, col0 = blockIdx.x * 128;
    float acc[2][8][4] = {};
    gemm_bt<LL/BK>(g_E + (size_t)b*LL*LL + (size_t)row0 * LL, LL,
                   g_SinT + ((size_t)b*YD + col0) * LL, LL, acc, As, Bs);
    const int lane = threadIdx.x & 31, warp = threadIdx.x >> 5;
    const int wm = (warp & 3) * 32, wn = (warp >> 2) * 64;
    const int qr = lane >> 2, qc = lane & 3;
    #pragma unroll
    for (int m = 0; m < 2; m++)
        #pragma unroll
        for (int rr = 0; rr < 2; rr++) {
            int row = row0 + wm + m*16 + qr + rr*8;
            float rinv = 1.f / g_R[b*LL + row];
            #pragma unroll
            for (int n = 0; n < 8; n++) {
                int col = col0 + wn + n*8 + 2*qc;
                float2 v;
                v.x = acc[m][n][rr*2+0] * rinv;
                v.y = acc[m][n][rr*2+1] * rinv;
                *(float2*)&out[((size_t)b*LL + row)*YD + col] = v;
            }
        }
}

// ============================================================
// K5a/K5b: temp_Qins two-stage mean
// ============================================================
__global__ __launch_bounds__(256) void k5a() {
    const int b = blockIdx.x, lc = blockIdx.y;
    const int t = threadIdx.x;
    const int q = t & 63, part = t >> 6;
    float s = 0.f;
    #pragma unroll
    for (int d = 0; d < ND; d++) {
        const float* base = g_Q + (((size_t)d*BB + b)*LL + lc*128) * QDIM;
        for (int l = part; l < 128; l += 4) s += base[(size_t)l * QDIM + q];
    }
    __shared__ float red[256];
    red[t] = s;
    __syncthreads();
    if (part == 0)
        g_TQp[(b*8 + lc)*QDIM + q] = red[q] + red[64+q] + red[128+q] + red[192+q];
}
__global__ void k5b(float* __restrict__ out2) {
    const int b = blockIdx.x, q = threadIdx.x;
    float s = 0.f;
    #pragma unroll
    for (int lc = 0; lc < 8; lc++) s += g_TQp[(b*8 + lc)*QDIM + q];
    out2[b*QDIM + q] = s * (1.f / (ND * (float)LL));
}

// ============================================================
extern "C" void kernel_launch(void* const* d_in, const int* in_sizes, int n_in,
                              void* d_out, int out_size) {
    const float* X    = (const float*)d_in[0];
    const float* mask = (const float*)d_in[1];
    const float* Wq   = (const float*)d_in[2];
    const float* bq   = (const float*)d_in[3];
    const float* Wh   = (const float*)d_in[4];
    const float* bh   = (const float*)d_in[5];
    const float* Ws   = (const float*)d_in[6];
    const float* bs   = (const float*)d_in[7];
    float* out = (float*)d_out;

    float* gX; cudaGetSymbolAddress((void**)&gX, g_X);
    float* gWq; cudaGetSymbolAddress((void**)&gWq, g_Wq);
    float* gWh; cudaGetSymbolAddress((void**)&gWh, g_Wh);
    float* gWs; cudaGetSymbolAddress((void**)&gWs, g_Ws);

    kround<<<MTOT*XD/1024, 256>>>(X, gX, MTOT*XD);
    kround<<<ND*QDIM*XD/1024, 256>>>(Wq, gWq, ND*QDIM*XD);
    kround<<<HL*XD/1024, 256>>>(Wh, gWh, HL*XD);
    kround<<<YD*HL/1024, 256>>>(Ws, gWs, YD*HL);
    kzero<<<64, 256>>>();
    k1_qproj<<<dim3(2, 128), 256>>>(bq);
    k2a_h<<<dim3(1, 128), 256>>>(bh);
    k2b_sin<<<dim3(4, 128), 256>>>(bs);
    k3_logits<<<dim3(16, 8, 16), 256>>>(mask);
    k4_pv<<<dim3(4, 8, 16), 256>>>(out);
    k5a<<<dim3(16, 8), 256>>>();
    k5b<<<16, 64>>>(out + (size_t)BB * LL * YD);
}

// round 11
// speedup vs baseline: 2.6320x; 1.0633x over previous
#include <cuda_runtime.h>
#include <cuda_bf16.h>
#include <cstdint>

#define LL 1024
#define BB 16
#define XD 512
#define YD 512
#define QDIM 64
#define ND 4
#define HL 128
#define MTOT (LL*BB)
#define RSQRT512 0.04419417382415922f

#define BK 16
#define ALD 20                    // padded [row][k] float stride
#define A_STAGE (128*ALD)
#define K3_BSTAGE (64*ALD)

// -------- scratch (device globals; no allocation allowed) --------
__device__ float g_X  [MTOT*XD];              // tf32-rounded X
__device__ float g_Wq [ND*QDIM*XD];
__device__ float g_Wh [HL*XD];
__device__ float g_Ws [YD*HL];
__device__ float g_Q  [ND*BB*LL*QDIM];        // [d][b][l][q] (rounded)
__device__ float g_sq [ND*BB*LL];
__device__ float g_h  [MTOT*HL];              // (rounded)
__device__ __nv_bfloat16 g_SinT[(size_t)BB*YD*LL];  // [b][y][l] bf16
__device__ __nv_bfloat16 g_E  [(size_t)BB*LL*LL];   // [b][i][j] bf16
__device__ float g_R  [BB*LL];
__device__ float g_TQp[BB*8*QDIM];

__device__ __forceinline__ void cp16(void* dst, const void* src) {
    uint32_t d = (uint32_t)__cvta_generic_to_shared(dst);
    asm volatile("cp.async.cg.shared.global [%0], [%1], 16;" :: "r"(d), "l"(src));
}
#define CP_COMMIT asm volatile("cp.async.commit_group;")
#define CP_WAIT0  asm volatile("cp.async.wait_group 0;")
#define CP_WAIT1  asm volatile("cp.async.wait_group 1;")

__device__ __forceinline__ uint32_t f2tf(float f) {
    uint32_t r; asm("cvt.rna.tf32.f32 %0, %1;" : "=r"(r) : "f"(f)); return r;
}
__device__ __forceinline__ float rtf(float f) { return __uint_as_float(f2tf(f)); }

__device__ __forceinline__ void ldsm4(uint32_t r[4], uint32_t addr) {
    asm volatile("ldmatrix.sync.aligned.m8n8.x4.shared.b16 {%0,%1,%2,%3}, [%4];"
        : "=r"(r[0]), "=r"(r[1]), "=r"(r[2]), "=r"(r[3]) : "r"(addr));
}
__device__ __forceinline__ void mma_tf32(float c[4], const uint32_t a[4],
                                         uint32_t b0, uint32_t b1) {
    asm volatile("mma.sync.aligned.m16n8k8.row.col.f32.tf32.tf32.f32 "
        "{%0,%1,%2,%3}, {%4,%5,%6,%7}, {%8,%9}, {%0,%1,%2,%3};"
        : "+f"(c[0]), "+f"(c[1]), "+f"(c[2]), "+f"(c[3])
        : "r"(a[0]), "r"(a[1]), "r"(a[2]), "r"(a[3]), "r"(b0), "r"(b1));
}
__device__ __forceinline__ void mma_bf16(float c[4], const uint32_t a[4],
                                         uint32_t b0, uint32_t b1) {
    asm volatile("mma.sync.aligned.m16n8k16.row.col.f32.bf16.bf16.f32 "
        "{%0,%1,%2,%3}, {%4,%5,%6,%7}, {%8,%9}, {%0,%1,%2,%3};"
        : "+f"(c[0]), "+f"(c[1]), "+f"(c[2]), "+f"(c[3])
        : "r"(a[0]), "r"(a[1]), "r"(a[2]), "r"(a[3]), "r"(b0), "r"(b1));
}

// ---------------- 3-stage pipelined 128x128 tf32 GEMM, BT form + ldmatrix ----
template<int NIT>
__device__ __forceinline__ void gemm_bt(const float* __restrict__ A, int lda,
                                        const float* __restrict__ Bg, int ldb,
                                        float acc[2][8][4], float* As, float* Bs)
{
    const int tid = threadIdx.x;
    const int lane = tid & 31, warp = tid >> 5;
    const int wm = (warp & 3) * 32, wn = (warp >> 2) * 64;
    const int r2  = (tid*2) >> 2,   k42  = ((tid*2)   & 3) * 4;
    const int r2b = (tid*2+1) >> 2, k42b = ((tid*2+1) & 3) * 4;
    const uint32_t aSm = (uint32_t)__cvta_generic_to_shared(As);
    const uint32_t bSm = (uint32_t)__cvta_generic_to_shared(Bs);
    uint32_t offA[2], offB[4];
    #pragma unroll
    for (int m = 0; m < 2; m++)
        offA[m] = ((wm + m*16 + (lane & 15))*ALD + ((lane & 16) >> 2)) * 4;
    #pragma unroll
    for (int p = 0; p < 4; p++)
        offB[p] = ((wn + p*16 + (lane & 7) + ((lane & 16) >> 1))*ALD + ((lane & 8) >> 1)) * 4;

    #define ISSUE(s, k0) do {                                                        \
        cp16(&As[(s)*A_STAGE + r2 *ALD + k42 ], A  + (size_t)r2 *lda + (k0) + k42 ); \
        cp16(&As[(s)*A_STAGE + r2b*ALD + k42b], A  + (size_t)r2b*lda + (k0) + k42b); \
        cp16(&Bs[(s)*A_STAGE + r2 *ALD + k42 ], Bg + (size_t)r2 *ldb + (k0) + k42 ); \
        cp16(&Bs[(s)*A_STAGE + r2b*ALD + k42b], Bg + (size_t)r2b*ldb + (k0) + k42b); \
        CP_COMMIT;                                                                   \
    } while (0)

    ISSUE(0, 0);
    ISSUE(1, BK);
    for (int it = 0; it < NIT; ++it) {
        if (it + 1 < NIT) { CP_WAIT1; } else { CP_WAIT0; }
        __syncthreads();
        if (it + 2 < NIT) ISSUE((it + 2) % 3, (it + 2) * BK);
        const uint32_t aB = aSm + (it % 3) * (A_STAGE * 4);
        const uint32_t bB = bSm + (it % 3) * (A_STAGE * 4);
        #pragma unroll
        for (int kk = 0; kk < 2; kk++) {
            uint32_t af[2][4];
            ldsm4(af[0], aB + offA[0] + kk*32);
            ldsm4(af[1], aB + offA[1] + kk*32);
            uint32_t bf[4][4];
            #pragma unroll
            for (int p = 0; p < 4; p++) ldsm4(bf[p], bB + offB[p] + kk*32);
            #pragma unroll
            for (int m = 0; m < 2; m++)
                #pragma unroll
                for (int n = 0; n < 8; n++)
                    mma_tf32(acc[m][n], af[m], bf[n>>1][(n&1)*2], bf[n>>1][(n&1)*2+1]);
        }
    }
    #undef ISSUE
}

// ============================================================
__global__ void kround(const float* __restrict__ src, float* __restrict__ dst, int n) {
    int i = (blockIdx.x * 256 + threadIdx.x) * 4;
    if (i < n) {
        float4 v = *(const float4*)(src + i);
        v.x = rtf(v.x); v.y = rtf(v.y); v.z = rtf(v.z); v.w = rtf(v.w);
        *(float4*)(dst + i) = v;
    }
}
__global__ void kzero() {
    int i = blockIdx.x * 256 + threadIdx.x;
    if (i < BB*LL) g_R[i] = 0.f;
}

// ============================================================
// K1: Qins = X @ Wq^T + bq -> g_Q (rounded), fused sq
// ============================================================
__global__ __launch_bounds__(256, 2) void k1_qproj(const float* __restrict__ bq) {
    __shared__ float As[3*A_STAGE], Bs[3*A_STAGE];
    const int row0 = blockIdx.y * 128, col0 = blockIdx.x * 128;
    float acc[2][8][4] = {};
    gemm_bt<XD/BK>(g_X + (size_t)row0 * XD, XD, g_Wq + (size_t)col0 * XD, XD, acc, As, Bs);
    const int lane = threadIdx.x & 31, warp = threadIdx.x >> 5;
    const int wm = (warp & 3) * 32, wn = (warp >> 2) * 64;
    const int qr = lane >> 2, qc = lane & 3;
    const int d = (col0 + wn) >> 6;
    #pragma unroll
    for (int m = 0; m < 2; m++)
        #pragma unroll
        for (int rr = 0; rr < 2; rr++) {
            int mrow = row0 + wm + m*16 + qr + rr*8;
            int l = mrow >> 4, b = mrow & 15;
            float s = 0.f;
            #pragma unroll
            for (int n = 0; n < 8; n++) {
                int cg = col0 + wn + n*8 + 2*qc;
                int q = cg & 63;
                float2 v;
                v.x = rtf(acc[m][n][rr*2+0] + bq[cg]);
                v.y = rtf(acc[m][n][rr*2+1] + bq[cg+1]);
                s += v.x*v.x + v.y*v.y;
                *(float2*)&g_Q[(((size_t)d*BB + b)*LL + l)*QDIM + q] = v;
            }
            s += __shfl_xor_sync(0xffffffffu, s, 1);
            s += __shfl_xor_sync(0xffffffffu, s, 2);
            if (qc == 0) g_sq[((size_t)d*BB + b)*LL + l] = s;
        }
}

// ============================================================
// K2a: h = sigmoid(X @ Wh^T + bh)  (rounded)
// ============================================================
__global__ __launch_bounds__(256, 2) void k2a_h(const float* __restrict__ bh) {
    __shared__ float As[3*A_STAGE], Bs[3*A_STAGE];
    const int row0 = blockIdx.y * 128;
    float acc[2][8][4] = {};
    gemm_bt<XD/BK>(g_X + (size_t)row0 * XD, XD, g_Wh, XD, acc, As, Bs);
    const int lane = threadIdx.x & 31, warp = threadIdx.x >> 5;
    const int wm = (warp & 3) * 32, wn = (warp >> 2) * 64;
    const int qr = lane >> 2, qc = lane & 3;
    #pragma unroll
    for (int m = 0; m < 2; m++)
        #pragma unroll
        for (int rr = 0; rr < 2; rr++) {
            int mrow = row0 + wm + m*16 + qr + rr*8;
            #pragma unroll
            for (int n = 0; n < 8; n++) {
                int cg = wn + n*8 + 2*qc;
                float2 v;
                v.x = rtf(1.f / (1.f + __expf(-(acc[m][n][rr*2+0] + bh[cg]))));
                v.y = rtf(1.f / (1.f + __expf(-(acc[m][n][rr*2+1] + bh[cg+1]))));
                *(float2*)&g_h[(size_t)mrow * HL + cg] = v;
            }
        }
}

// ============================================================
// K2b: Sin = h @ Ws^T + bs -> g_SinT[b][y][l]  (bf16, transposed)
// ============================================================
__global__ __launch_bounds__(256, 2) void k2b_sin(const float* __restrict__ bs) {
    __shared__ float As[3*A_STAGE], Bs[3*A_STAGE];
    const int row0 = blockIdx.y * 128, col0 = blockIdx.x * 128;
    float acc[2][8][4] = {};
    gemm_bt<HL/BK>(g_h + (size_t)row0 * HL, HL, g_Ws + (size_t)col0 * HL, HL, acc, As, Bs);
    const int lane = threadIdx.x & 31, warp = threadIdx.x >> 5;
    const int wm = (warp & 3) * 32, wn = (warp >> 2) * 64;
    const int qr = lane >> 2, qc = lane & 3;
    #pragma unroll
    for (int m = 0; m < 2; m++)
        #pragma unroll
        for (int rr = 0; rr < 2; rr++) {
            int mrow = row0 + wm + m*16 + qr + rr*8;
            int l = mrow >> 4, b = mrow & 15;
            #pragma unroll
            for (int n = 0; n < 8; n++) {
                int cg = col0 + wn + n*8 + 2*qc;
                g_SinT[((size_t)b*YD + cg  )*LL + l] = __float2bfloat16(acc[m][n][rr*2+0] + bs[cg]);
                g_SinT[((size_t)b*YD + cg+1)*LL + l] = __float2bfloat16(acc[m][n][rr*2+1] + bs[cg+1]);
            }
        }
}

// ============================================================
// K3: fused pairwise-distance logits -> E (bf16), fused rowsum
// ============================================================
__global__ __launch_bounds__(256, 2) void k3_logits(const float* __restrict__ mask) {
    __shared__ float As[3*A_STAGE], Bs[3*K3_BSTAGE];
    const int bI = blockIdx.z;
    const int i0 = blockIdx.y * 128, j0 = blockIdx.x * 64;
    const int tid = threadIdx.x;
    const int lane = tid & 31, warp = tid >> 5;
    const int wm = (warp & 3) * 32, wn = (warp >> 2) * 32;
    const int qr = lane >> 2, qc = lane & 3;

    const int r2  = (tid*2) >> 2,   k42  = ((tid*2)   & 3) * 4;
    const int r2b = (tid*2+1) >> 2, k42b = ((tid*2+1) & 3) * 4;
    const int bn  = tid >> 2, bk4 = (tid & 3) * 4;

    const uint32_t aSm = (uint32_t)__cvta_generic_to_shared(As);
    const uint32_t bSm = (uint32_t)__cvta_generic_to_shared(Bs);
    uint32_t offA[2], offB[2];
    #pragma unroll
    for (int m = 0; m < 2; m++)
        offA[m] = ((wm + m*16 + (lane & 15))*ALD + ((lane & 16) >> 2)) * 4;
    #pragma unroll
    for (int p = 0; p < 2; p++)
        offB[p] = ((wn + p*16 + (lane & 7) + ((lane & 16) >> 1))*ALD + ((lane & 8) >> 1)) * 4;

    #define K3_ISSUE(s, t) do {                                                     \
        int d_ = (t) >> 2, ko_ = ((t) & 3) * BK;                                    \
        const float* Ab_ = g_Q + (((size_t)d_*BB + bI)*LL + i0) * QDIM + ko_;       \
        const float* Bb_ = g_Q + (((size_t)d_*BB + bI)*LL + j0) * QDIM + ko_;       \
        cp16(&As[(s)*A_STAGE + r2 *ALD + k42 ], Ab_ + (size_t)r2 *QDIM + k42 );     \
        cp16(&As[(s)*A_STAGE + r2b*ALD + k42b], Ab_ + (size_t)r2b*QDIM + k42b);     \
        cp16(&Bs[(s)*K3_BSTAGE + bn*ALD + bk4], Bb_ + (size_t)bn*QDIM + bk4);       \
        CP_COMMIT;                                                                  \
    } while (0)

    float logit[2][4][4] = {};
    float acc[2][4][4] = {};
    K3_ISSUE(0, 0);
    K3_ISSUE(1, 1);
    for (int t = 0; t < 16; ++t) {
        if (t + 1 < 16) { CP_WAIT1; } else { CP_WAIT0; }
        __syncthreads();
        if (t + 2 < 16) K3_ISSUE((t + 2) % 3, t + 2);
        const uint32_t aB = aSm + (t % 3) * (A_STAGE * 4);
        const uint32_t bB = bSm + (t % 3) * (K3_BSTAGE * 4);
        #pragma unroll
        for (int kk = 0; kk < 2; kk++) {
            uint32_t af[2][4];
            ldsm4(af[0], aB + offA[0] + kk*32);
            ldsm4(af[1], aB + offA[1] + kk*32);
            uint32_t bf[2][4];
            ldsm4(bf[0], bB + offB[0] + kk*32);
            ldsm4(bf[1], bB + offB[1] + kk*32);
            #pragma unroll
            for (int m = 0; m < 2; m++)
                #pragma unroll
                for (int n = 0; n < 4; n++)
                    mma_tf32(acc[m][n], af[m], bf[n>>1][(n&1)*2], bf[n>>1][(n&1)*2+1]);
        }
        if ((t & 3) == 3) {
            const int d = t >> 2;
            const float sgn = (d & 1) ? -1.f : 1.f;
            const float* sqb = g_sq + ((size_t)d*BB + bI) * LL;
            #pragma unroll
            for (int m = 0; m < 2; m++)
                #pragma unroll
                for (int rr = 0; rr < 2; rr++) {
                    int gi = i0 + wm + m*16 + qr + rr*8;
                    float sqi = sqb[gi];
                    #pragma unroll
                    for (int n = 0; n < 4; n++) {
                        int gj = j0 + wn + n*8 + 2*qc;
                        float d20 = fmaxf(sqi + sqb[gj]   - 2.f*acc[m][n][rr*2+0], 0.f);
                        float d21 = fmaxf(sqi + sqb[gj+1] - 2.f*acc[m][n][rr*2+1], 0.f);
                        logit[m][n][rr*2+0] += (gi == gj)   ? 0.f : sgn * sqrtf(d20);
                        logit[m][n][rr*2+1] += (gi == gj+1) ? 0.f : sgn * sqrtf(d21);
                        acc[m][n][rr*2+0] = 0.f;
                        acc[m][n][rr*2+1] = 0.f;
                    }
                }
        }
    }
    #undef K3_ISSUE
    #pragma unroll
    for (int m = 0; m < 2; m++)
        #pragma unroll
        for (int rr = 0; rr < 2; rr++) {
            int gi = i0 + wm + m*16 + qr + rr*8;
            float s = 0.f;
            #pragma unroll
            for (int n = 0; n < 4; n++) {
                int gj = j0 + wn + n*8 + 2*qc;
                float2 mv = *(const float2*)&mask[(size_t)gi * LL + gj];
                float e0 = __expf(logit[m][n][rr*2+0] * RSQRT512 + mv.x);
                float e1 = __expf(logit[m][n][rr*2+1] * RSQRT512 + mv.y);
                __nv_bfloat162 p2;
                p2.x = __float2bfloat16(e0);
                p2.y = __float2bfloat16(e1);
                s += __bfloat162float(p2.x) + __bfloat162float(p2.y);
                *(__nv_bfloat162*)&g_E[((size_t)bI*LL + gi)*LL + gj] = p2;
            }
            s += __shfl_xor_sync(0xffffffffu, s, 1);
            s += __shfl_xor_sync(0xffffffffu, s, 2);
            if (qc == 0) atomicAdd(&g_R[bI*LL + gi], s);
        }
}

// ============================================================
// K4: Sout[b] = diag(1/R) * E[b] @ SinT[b]^T   — bf16 m16n8k16 path
// dynamic smem: 3 stages x (A 10KB + B 10KB) = 61440 B
// ============================================================
#define BK4 32
#define SLD 40                   // bf16 elems per row (80 B, conflict-free)
#define ST4 (128*SLD)            // bf16 elems per buffer
#define K4_SMEM (3*ST4*2*2)      // bytes
__global__ __launch_bounds__(256, 2) void k4_pv(float* __restrict__ out) {
    extern __shared__ __nv_bfloat16 dsm[];
    __nv_bfloat16* As4 = dsm;
    __nv_bfloat16* Bs4 = dsm + 3*ST4;
    const int b = blockIdx.z;
    const int row0 = blockIdx.y * 128, col0 = blockIdx.x * 128;
    const __nv_bfloat16* A = g_E + (size_t)b*LL*LL + (size_t)row0*LL;
    const __nv_bfloat16* Bg = g_SinT + ((size_t)b*YD + col0)*LL;
    const int tid = threadIdx.x;
    const int lane = tid & 31, warp = tid >> 5;
    const int wm = (warp & 3) * 32, wn = (warp >> 2) * 64;
    const int qr = lane >> 2, qc = lane & 3;
    const int ra  = (tid*2) >> 2,   ca  = ((tid*2)   & 3) * 8;
    const int rab = (tid*2+1) >> 2, cab = ((tid*2+1) & 3) * 8;
    const uint32_t aSm = (uint32_t)__cvta_generic_to_shared(As4);
    const uint32_t bSm = (uint32_t)__cvta_generic_to_shared(Bs4);
    uint32_t offA[2], offB[4];
    #pragma unroll
    for (int m = 0; m < 2; m++)
        offA[m] = ((wm + m*16 + (lane & 15))*SLD + ((lane & 16) >> 1)) * 2;
    #pragma unroll
    for (int p = 0; p < 4; p++)
        offB[p] = ((wn + p*16 + (lane & 7) + (lane & 8))*SLD + ((lane & 16) >> 1)) * 2;

    float acc[2][8][4] = {};
    #define K4_ISSUE(s, k0) do {                                                      \
        cp16(&As4[(s)*ST4 + ra *SLD + ca ], A  + (size_t)ra *LL + (k0) + ca );        \
        cp16(&As4[(s)*ST4 + rab*SLD + cab], A  + (size_t)rab*LL + (k0) + cab);        \
        cp16(&Bs4[(s)*ST4 + ra *SLD + ca ], Bg + (size_t)ra *LL + (k0) + ca );        \
        cp16(&Bs4[(s)*ST4 + rab*SLD + cab], Bg + (size_t)rab*LL + (k0) + cab);        \
        CP_COMMIT;                                                                    \
    } while (0)

    const int NIT = LL / BK4;     // 32
    K4_ISSUE(0, 0);
    K4_ISSUE(1, BK4);
    for (int it = 0; it < NIT; ++it) {
        if (it + 1 < NIT) { CP_WAIT1; } else { CP_WAIT0; }
        __syncthreads();
        if (it + 2 < NIT) K4_ISSUE((it + 2) % 3, (it + 2) * BK4);
        const uint32_t aB = aSm + (it % 3) * (ST4 * 2);
        const uint32_t bB = bSm + (it % 3) * (ST4 * 2);
        #pragma unroll
        for (int kk = 0; kk < 2; kk++) {      // two K=16 steps
            uint32_t af[2][4];
            ldsm4(af[0], aB + offA[0] + kk*32);
            ldsm4(af[1], aB + offA[1] + kk*32);
            uint32_t bf[4][4];
            #pragma unroll
            for (int p = 0; p < 4; p++) ldsm4(bf[p], bB + offB[p] + kk*32);
            #pragma unroll
            for (int m = 0; m < 2; m++)
                #pragma unroll
                for (int n = 0; n < 8; n++)
                    mma_bf16(acc[m][n], af[m], bf[n>>1][n&1], bf[n>>1][(n&1)+2]);
        }
    }
    #undef K4_ISSUE
    #pragma unroll
    for (int m = 0; m < 2; m++)
        #pragma unroll
        for (int rr = 0; rr < 2; rr++) {
            int row = row0 + wm + m*16 + qr + rr*8;
            float rinv = 1.f / g_R[b*LL + row];
            #pragma unroll
            for (int n = 0; n < 8; n++) {
                int col = col0 + wn + n*8 + 2*qc;
                float2 v;
                v.x = acc[m][n][rr*2+0] * rinv;
                v.y = acc[m][n][rr*2+1] * rinv;
                *(float2*)&out[((size_t)b*LL + row)*YD + col] = v;
            }
        }
}

// ============================================================
// K5a/K5b: temp_Qins two-stage mean
// ============================================================
__global__ __launch_bounds__(256) void k5a() {
    const int b = blockIdx.x, lc = blockIdx.y;
    const int t = threadIdx.x;
    const int q = t & 63, part = t >> 6;
    float s = 0.f;
    #pragma unroll
    for (int d = 0; d < ND; d++) {
        const float* base = g_Q + (((size_t)d*BB + b)*LL + lc*128) * QDIM;
        for (int l = part; l < 128; l += 4) s += base[(size_t)l * QDIM + q];
    }
    __shared__ float red[256];
    red[t] = s;
    __syncthreads();
    if (part == 0)
        g_TQp[(b*8 + lc)*QDIM + q] = red[q] + red[64+q] + red[128+q] + red[192+q];
}
__global__ void k5b(float* __restrict__ out2) {
    const int b = blockIdx.x, q = threadIdx.x;
    float s = 0.f;
    #pragma unroll
    for (int lc = 0; lc < 8; lc++) s += g_TQp[(b*8 + lc)*QDIM + q];
    out2[b*QDIM + q] = s * (1.f / (ND * (float)LL));
}

// ============================================================
extern "C" void kernel_launch(void* const* d_in, const int* in_sizes, int n_in,
                              void* d_out, int out_size) {
    const float* X    = (const float*)d_in[0];
    const float* mask = (const float*)d_in[1];
    const float* Wq   = (const float*)d_in[2];
    const float* bq   = (const float*)d_in[3];
    const float* Wh   = (const float*)d_in[4];
    const float* bh   = (const float*)d_in[5];
    const float* Ws   = (const float*)d_in[6];
    const float* bs   = (const float*)d_in[7];
    float* out = (float*)d_out;

    float* gX;  cudaGetSymbolAddress((void**)&gX,  g_X);
    float* gWq; cudaGetSymbolAddress((void**)&gWq, g_Wq);
    float* gWh; cudaGetSymbolAddress((void**)&gWh, g_Wh);
    float* gWs; cudaGetSymbolAddress((void**)&gWs, g_Ws);

    cudaFuncSetAttribute(k4_pv, cudaFuncAttributeMaxDynamicSharedMemorySize, K4_SMEM);

    kround<<<MTOT*XD/1024, 256>>>(X, gX, MTOT*XD);
    kround<<<ND*QDIM*XD/1024, 256>>>(Wq, gWq, ND*QDIM*XD);
    kround<<<HL*XD/1024, 256>>>(Wh, gWh, HL*XD);
    kround<<<YD*HL/1024, 256>>>(Ws, gWs, YD*HL);
    kzero<<<64, 256>>>();
    k1_qproj<<<dim3(2, 128), 256>>>(bq);
    k2a_h<<<dim3(1, 128), 256>>>(bh);
    k2b_sin<<<dim3(4, 128), 256>>>(bs);
    k3_logits<<<dim3(16, 8, 16), 256>>>(mask);
    k4_pv<<<dim3(4, 8, 16), 256, K4_SMEM>>>(out);
    k5a<<<dim3(16, 8), 256>>>();
    k5b<<<16, 64>>>(out + (size_t)BB * LL * YD);
}

// round 12
// speedup vs baseline: 3.3061x; 1.2561x over previous
#include <cuda_runtime.h>
#include <cuda_fp16.h>
#include <cstdint>

#define LL 1024
#define BB 16
#define XD 512
#define YD 512
#define QDIM 64
#define ND 4
#define HL 128
#define MTOT (LL*BB)
#define RSQRT512 0.04419417382415922f

#define BK 16
#define ALD 20                    // padded [row][k] float stride (tf32 GEMMs)
#define A_STAGE (128*ALD)

// -------- scratch (device globals; no allocation allowed) --------
__device__ float g_X  [MTOT*XD];              // tf32-rounded X
__device__ float g_Wq [ND*QDIM*XD];
__device__ float g_Wh [HL*XD];
__device__ float g_Ws [YD*HL];
__device__ __half g_Qh[ND*BB*LL*QDIM];        // [d][b][l][q] fp16
__device__ float g_sq [ND*BB*LL];             // from fp16-rounded Q
__device__ float g_h  [MTOT*HL];              // tf32-rounded
__device__ __half g_SinT[(size_t)BB*YD*LL];   // [b][y][l] fp16
__device__ __half g_E  [(size_t)BB*LL*LL];    // [b][i][j] fp16
__device__ float g_R  [BB*LL];
__device__ float g_TQp[BB*8*QDIM];

__device__ __forceinline__ void cp16(void* dst, const void* src) {
    uint32_t d = (uint32_t)__cvta_generic_to_shared(dst);
    asm volatile("cp.async.cg.shared.global [%0], [%1], 16;" :: "r"(d), "l"(src));
}
#define CP_COMMIT asm volatile("cp.async.commit_group;")
#define CP_WAIT0  asm volatile("cp.async.wait_group 0;")
#define CP_WAIT1  asm volatile("cp.async.wait_group 1;")

__device__ __forceinline__ uint32_t f2tf(float f) {
    uint32_t r; asm("cvt.rna.tf32.f32 %0, %1;" : "=r"(r) : "f"(f)); return r;
}
__device__ __forceinline__ float rtf(float f) { return __uint_as_float(f2tf(f)); }
__device__ __forceinline__ float sqrt_ap(float f) {
    float r; asm("sqrt.approx.f32 %0, %1;" : "=f"(r) : "f"(f)); return r;
}

__device__ __forceinline__ void ldsm4(uint32_t r[4], uint32_t addr) {
    asm volatile("ldmatrix.sync.aligned.m8n8.x4.shared.b16 {%0,%1,%2,%3}, [%4];"
        : "=r"(r[0]), "=r"(r[1]), "=r"(r[2]), "=r"(r[3]) : "r"(addr));
}
__device__ __forceinline__ void mma_tf32(float c[4], const uint32_t a[4],
                                         uint32_t b0, uint32_t b1) {
    asm volatile("mma.sync.aligned.m16n8k8.row.col.f32.tf32.tf32.f32 "
        "{%0,%1,%2,%3}, {%4,%5,%6,%7}, {%8,%9}, {%0,%1,%2,%3};"
        : "+f"(c[0]), "+f"(c[1]), "+f"(c[2]), "+f"(c[3])
        : "r"(a[0]), "r"(a[1]), "r"(a[2]), "r"(a[3]), "r"(b0), "r"(b1));
}
__device__ __forceinline__ void mma_f16(float c[4], const uint32_t a[4],
                                        uint32_t b0, uint32_t b1) {
    asm volatile("mma.sync.aligned.m16n8k16.row.col.f32.f16.f16.f32 "
        "{%0,%1,%2,%3}, {%4,%5,%6,%7}, {%8,%9}, {%0,%1,%2,%3};"
        : "+f"(c[0]), "+f"(c[1]), "+f"(c[2]), "+f"(c[3])
        : "r"(a[0]), "r"(a[1]), "r"(a[2]), "r"(a[3]), "r"(b0), "r"(b1));
}

// ---------------- 3-stage pipelined 128x128 tf32 GEMM, BT form + ldmatrix ----
template<int NIT>
__device__ __forceinline__ void gemm_bt(const float* __restrict__ A, int lda,
                                        const float* __restrict__ Bg, int ldb,
                                        float acc[2][8][4], float* As, float* Bs)
{
    const int tid = threadIdx.x;
    const int lane = tid & 31, warp = tid >> 5;
    const int wm = (warp & 3) * 32, wn = (warp >> 2) * 64;
    const int r2  = (tid*2) >> 2,   k42  = ((tid*2)   & 3) * 4;
    const int r2b = (tid*2+1) >> 2, k42b = ((tid*2+1) & 3) * 4;
    const uint32_t aSm = (uint32_t)__cvta_generic_to_shared(As);
    const uint32_t bSm = (uint32_t)__cvta_generic_to_shared(Bs);
    uint32_t offA[2], offB[4];
    #pragma unroll
    for (int m = 0; m < 2; m++)
        offA[m] = ((wm + m*16 + (lane & 15))*ALD + ((lane & 16) >> 2)) * 4;
    #pragma unroll
    for (int p = 0; p < 4; p++)
        offB[p] = ((wn + p*16 + (lane & 7) + ((lane & 16) >> 1))*ALD + ((lane & 8) >> 1)) * 4;

    #define ISSUE(s, k0) do {                                                        \
        cp16(&As[(s)*A_STAGE + r2 *ALD + k42 ], A  + (size_t)r2 *lda + (k0) + k42 ); \
        cp16(&As[(s)*A_STAGE + r2b*ALD + k42b], A  + (size_t)r2b*lda + (k0) + k42b); \
        cp16(&Bs[(s)*A_STAGE + r2 *ALD + k42 ], Bg + (size_t)r2 *ldb + (k0) + k42 ); \
        cp16(&Bs[(s)*A_STAGE + r2b*ALD + k42b], Bg + (size_t)r2b*ldb + (k0) + k42b); \
        CP_COMMIT;                                                                   \
    } while (0)

    ISSUE(0, 0);
    ISSUE(1, BK);
    for (int it = 0; it < NIT; ++it) {
        if (it + 1 < NIT) { CP_WAIT1; } else { CP_WAIT0; }
        __syncthreads();
        if (it + 2 < NIT) ISSUE((it + 2) % 3, (it + 2) * BK);
        const uint32_t aB = aSm + (it % 3) * (A_STAGE * 4);
        const uint32_t bB = bSm + (it % 3) * (A_STAGE * 4);
        #pragma unroll
        for (int kk = 0; kk < 2; kk++) {
            uint32_t af[2][4];
            ldsm4(af[0], aB + offA[0] + kk*32);
            ldsm4(af[1], aB + offA[1] + kk*32);
            uint32_t bf[4][4];
            #pragma unroll
            for (int p = 0; p < 4; p++) ldsm4(bf[p], bB + offB[p] + kk*32);
            #pragma unroll
            for (int m = 0; m < 2; m++)
                #pragma unroll
                for (int n = 0; n < 8; n++)
                    mma_tf32(acc[m][n], af[m], bf[n>>1][(n&1)*2], bf[n>>1][(n&1)*2+1]);
        }
    }
    #undef ISSUE
}

// ============================================================
// kround: X; kprep: weights + R-zero merged
// ============================================================
__global__ void kround(const float* __restrict__ src, float* __restrict__ dst, int n) {
    int i = (blockIdx.x * 256 + threadIdx.x) * 4;
    if (i < n) {
        float4 v = *(const float4*)(src + i);
        v.x = rtf(v.x); v.y = rtf(v.y); v.z = rtf(v.z); v.w = rtf(v.w);
        *(float4*)(dst + i) = v;
    }
}
__global__ void kprep(const float* __restrict__ Wq, const float* __restrict__ Wh,
                      const float* __restrict__ Ws) {
    int i = (blockIdx.x * 256 + threadIdx.x) * 4;
    const float* s; float* d; int j;
    if (i < 131072)      { s = Wq; d = g_Wq; j = i; }
    else if (i < 196608) { s = Wh; d = g_Wh; j = i - 131072; }
    else if (i < 262144) { s = Ws; d = g_Ws; j = i - 196608; }
    else if (i < 278528) { j = i - 262144; *(float4*)&g_R[j] = make_float4(0,0,0,0); return; }
    else return;
    float4 v = *(const float4*)(s + j);
    v.x = rtf(v.x); v.y = rtf(v.y); v.z = rtf(v.z); v.w = rtf(v.w);
    *(float4*)(d + j) = v;
}

// ============================================================
// K1: Qins = X @ Wq^T + bq -> g_Qh (fp16), fused sq (from fp16 values)
// ============================================================
__global__ __launch_bounds__(256, 2) void k1_qproj(const float* __restrict__ bq) {
    __shared__ float As[3*A_STAGE], Bs[3*A_STAGE];
    const int row0 = blockIdx.y * 128, col0 = blockIdx.x * 128;
    float acc[2][8][4] = {};
    gemm_bt<XD/BK>(g_X + (size_t)row0 * XD, XD, g_Wq + (size_t)col0 * XD, XD, acc, As, Bs);
    const int lane = threadIdx.x & 31, warp = threadIdx.x >> 5;
    const int wm = (warp & 3) * 32, wn = (warp >> 2) * 64;
    const int qr = lane >> 2, qc = lane & 3;
    const int d = (col0 + wn) >> 6;
    #pragma unroll
    for (int m = 0; m < 2; m++)
        #pragma unroll
        for (int rr = 0; rr < 2; rr++) {
            int mrow = row0 + wm + m*16 + qr + rr*8;
            int l = mrow >> 4, b = mrow & 15;
            float s = 0.f;
            #pragma unroll
            for (int n = 0; n < 8; n++) {
                int cg = col0 + wn + n*8 + 2*qc;
                int q = cg & 63;
                __half2 hv = __floats2half2_rn(acc[m][n][rr*2+0] + bq[cg],
                                               acc[m][n][rr*2+1] + bq[cg+1]);
                float vx = __half2float(__low2half(hv));
                float vy = __half2float(__high2half(hv));
                s += vx*vx + vy*vy;
                *(__half2*)&g_Qh[(((size_t)d*BB + b)*LL + l)*QDIM + q] = hv;
            }
            s += __shfl_xor_sync(0xffffffffu, s, 1);
            s += __shfl_xor_sync(0xffffffffu, s, 2);
            if (qc == 0) g_sq[((size_t)d*BB + b)*LL + l] = s;
        }
}

// ============================================================
// K2a: h = sigmoid(X @ Wh^T + bh)  (tf32-rounded)
// ============================================================
__global__ __launch_bounds__(256, 2) void k2a_h(const float* __restrict__ bh) {
    __shared__ float As[3*A_STAGE], Bs[3*A_STAGE];
    const int row0 = blockIdx.y * 128;
    float acc[2][8][4] = {};
    gemm_bt<XD/BK>(g_X + (size_t)row0 * XD, XD, g_Wh, XD, acc, As, Bs);
    const int lane = threadIdx.x & 31, warp = threadIdx.x >> 5;
    const int wm = (warp & 3) * 32, wn = (warp >> 2) * 64;
    const int qr = lane >> 2, qc = lane & 3;
    #pragma unroll
    for (int m = 0; m < 2; m++)
        #pragma unroll
        for (int rr = 0; rr < 2; rr++) {
            int mrow = row0 + wm + m*16 + qr + rr*8;
            #pragma unroll
            for (int n = 0; n < 8; n++) {
                int cg = wn + n*8 + 2*qc;
                float2 v;
                v.x = rtf(1.f / (1.f + __expf(-(acc[m][n][rr*2+0] + bh[cg]))));
                v.y = rtf(1.f / (1.f + __expf(-(acc[m][n][rr*2+1] + bh[cg+1]))));
                *(float2*)&g_h[(size_t)mrow * HL + cg] = v;
            }
        }
}

// ============================================================
// K2b: Sin = h @ Ws^T + bs -> g_SinT[b][y][l]  (fp16, transposed)
// ============================================================
__global__ __launch_bounds__(256, 2) void k2b_sin(const float* __restrict__ bs) {
    __shared__ float As[3*A_STAGE], Bs[3*A_STAGE];
    const int row0 = blockIdx.y * 128, col0 = blockIdx.x * 128;
    float acc[2][8][4] = {};
    gemm_bt<HL/BK>(g_h + (size_t)row0 * HL, HL, g_Ws + (size_t)col0 * HL, HL, acc, As, Bs);
    const int lane = threadIdx.x & 31, warp = threadIdx.x >> 5;
    const int wm = (warp & 3) * 32, wn = (warp >> 2) * 64;
    const int qr = lane >> 2, qc = lane & 3;
    #pragma unroll
    for (int m = 0; m < 2; m++)
        #pragma unroll
        for (int rr = 0; rr < 2; rr++) {
            int mrow = row0 + wm + m*16 + qr + rr*8;
            int l = mrow >> 4, b = mrow & 15;
            #pragma unroll
            for (int n = 0; n < 8; n++) {
                int cg = col0 + wn + n*8 + 2*qc;
                g_SinT[((size_t)b*YD + cg  )*LL + l] = __float2half(acc[m][n][rr*2+0] + bs[cg]);
                g_SinT[((size_t)b*YD + cg+1)*LL + l] = __float2half(acc[m][n][rr*2+1] + bs[cg+1]);
            }
        }
}

// ============================================================
// K3: fp16 Gram (m16n8k16) -> logits -> E (fp16), fused rowsum
// 128(i) x 64(j) tiles; 3-stage pipeline over 4 d's; full K=64 per tile.
// smem tile: A 128x64h (XOR-swizzled 128B rows, 16KB) + B 64x64h (8KB)
// ============================================================
#define K3_STAGE 24576
#define K3_SMEM  (3*K3_STAGE)
__global__ __launch_bounds__(256, 2) void k3_logits(const float* __restrict__ mask) {
    extern __shared__ char sm3[];
    const int bI = blockIdx.z;
    const int i0 = blockIdx.y * 128, j0 = blockIdx.x * 64;
    const int tid = threadIdx.x;
    const int lane = tid & 31, warp = tid >> 5;
    const int wm = (warp & 3) * 32, wn = (warp >> 2) * 32;
    const int qr = lane >> 2, qc = lane & 3;
    const uint32_t smU = (uint32_t)__cvta_generic_to_shared(sm3);

    #define K3_LD(s, d_) do {                                                        \
        const __half* Ab_ = g_Qh + (((size_t)(d_)*BB + bI)*LL + i0) * QDIM;          \
        const __half* Bb_ = g_Qh + (((size_t)(d_)*BB + bI)*LL + j0) * QDIM;          \
        char* st_ = sm3 + (s)*K3_STAGE;                                              \
        _Pragma("unroll")                                                            \
        for (int i_ = 0; i_ < 6; i_++) {                                             \
            int u_ = tid + i_*256;                                                   \
            if (u_ < 1024) {                                                         \
                int row_ = u_ >> 3, c_ = u_ & 7;                                     \
                cp16(st_ + row_*128 + ((c_ ^ (row_ & 7)) << 4),                      \
                     Ab_ + (size_t)row_*QDIM + c_*8);                                \
            } else {                                                                 \
                int v_ = u_ - 1024;                                                  \
                int row_ = v_ >> 3, c_ = v_ & 7;                                     \
                cp16(st_ + 16384 + row_*128 + ((c_ ^ (row_ & 7)) << 4),              \
                     Bb_ + (size_t)row_*QDIM + c_*8);                                \
            }                                                                        \
        }                                                                            \
        CP_COMMIT;                                                                   \
    } while (0)

    float logit[2][4][4] = {};
    K3_LD(0, 0);
    K3_LD(1, 1);
    const int la7 = lane & 7, hi = (lane >> 4) & 1;
    for (int d = 0; d < ND; d++) {
        if (d + 1 < ND) { CP_WAIT1; } else { CP_WAIT0; }
        __syncthreads();
        if (d + 2 < ND) K3_LD((d + 2) % 3, d + 2);
        const uint32_t aB = smU + (d % 3) * K3_STAGE;
        const uint32_t bB = aB + 16384;
        float acc[2][4][4] = {};
        #pragma unroll
        for (int kk = 0; kk < 4; kk++) {
            int sw = ((kk*2 + hi) ^ la7) << 4;
            uint32_t af[2][4];
            #pragma unroll
            for (int m = 0; m < 2; m++) {
                int row = wm + m*16 + (lane & 15);
                ldsm4(af[m], aB + row*128 + (((kk*2 + hi) ^ (row & 7)) << 4));
            }
            uint32_t bf[2][4];
            #pragma unroll
            for (int p = 0; p < 2; p++) {
                int row = wn + p*16 + la7 + (lane & 8);
                ldsm4(bf[p], bB + row*128 + sw);
            }
            #pragma unroll
            for (int m = 0; m < 2; m++)
                #pragma unroll
                for (int n = 0; n < 4; n++)
                    mma_f16(acc[m][n], af[m], bf[n>>1][n&1], bf[n>>1][(n&1)+2]);
        }
        const float sgn = (d & 1) ? -1.f : 1.f;
        const float* sqb = g_sq + ((size_t)d*BB + bI) * LL;
        #pragma unroll
        for (int m = 0; m < 2; m++)
            #pragma unroll
            for (int rr = 0; rr < 2; rr++) {
                int gi = i0 + wm + m*16 + qr + rr*8;
                float sqi = sqb[gi];
                #pragma unroll
                for (int n = 0; n < 4; n++) {
                    int gj = j0 + wn + n*8 + 2*qc;
                    float d20 = fmaxf(sqi + sqb[gj]   - 2.f*acc[m][n][rr*2+0], 0.f);
                    float d21 = fmaxf(sqi + sqb[gj+1] - 2.f*acc[m][n][rr*2+1], 0.f);
                    logit[m][n][rr*2+0] += (gi == gj)   ? 0.f : sgn * sqrt_ap(d20);
                    logit[m][n][rr*2+1] += (gi == gj+1) ? 0.f : sgn * sqrt_ap(d21);
                }
            }
    }
    #undef K3_LD
    #pragma unroll
    for (int m = 0; m < 2; m++)
        #pragma unroll
        for (int rr = 0; rr < 2; rr++) {
            int gi = i0 + wm + m*16 + qr + rr*8;
            float s = 0.f;
            #pragma unroll
            for (int n = 0; n < 4; n++) {
                int gj = j0 + wn + n*8 + 2*qc;
                float2 mv = *(const float2*)&mask[(size_t)gi * LL + gj];
                float e0 = __expf(logit[m][n][rr*2+0] * RSQRT512 + mv.x);
                float e1 = __expf(logit[m][n][rr*2+1] * RSQRT512 + mv.y);
                __half2 p2 = __floats2half2_rn(e0, e1);
                s += __half2float(__low2half(p2)) + __half2float(__high2half(p2));
                *(__half2*)&g_E[((size_t)bI*LL + gi)*LL + gj] = p2;
            }
            s += __shfl_xor_sync(0xffffffffu, s, 1);
            s += __shfl_xor_sync(0xffffffffu, s, 2);
            if (qc == 0) atomicAdd(&g_R[bI*LL + gi], s);
        }
}

// ============================================================
// K4: Sout[b] = diag(1/R) * E[b] @ SinT[b]^T   — fp16 m16n8k16
// ============================================================
#define BK4 32
#define SLD 40
#define ST4 (128*SLD)
#define K4_SMEM (3*ST4*2*2)
__global__ __launch_bounds__(256, 2) void k4_pv(float* __restrict__ out) {
    extern __shared__ __half dsm[];
    __half* As4 = dsm;
    __half* Bs4 = dsm + 3*ST4;
    const int b = blockIdx.z;
    const int row0 = blockIdx.y * 128, col0 = blockIdx.x * 128;
    const __half* A = g_E + (size_t)b*LL*LL + (size_t)row0*LL;
    const __half* Bg = g_SinT + ((size_t)b*YD + col0)*LL;
    const int tid = threadIdx.x;
    const int lane = tid & 31, warp = tid >> 5;
    const int wm = (warp & 3) * 32, wn = (warp >> 2) * 64;
    const int qr = lane >> 2, qc = lane & 3;
    const int ra  = (tid*2) >> 2,   ca  = ((tid*2)   & 3) * 8;
    const int rab = (tid*2+1) >> 2, cab = ((tid*2+1) & 3) * 8;
    const uint32_t aSm = (uint32_t)__cvta_generic_to_shared(As4);
    const uint32_t bSm = (uint32_t)__cvta_generic_to_shared(Bs4);
    uint32_t offA[2], offB[4];
    #pragma unroll
    for (int m = 0; m < 2; m++)
        offA[m] = ((wm + m*16 + (lane & 15))*SLD + ((lane & 16) >> 1)) * 2;
    #pragma unroll
    for (int p = 0; p < 4; p++)
        offB[p] = ((wn + p*16 + (lane & 7) + (lane & 8))*SLD + ((lane & 16) >> 1)) * 2;

    float acc[2][8][4] = {};
    #define K4_ISSUE(s, k0) do {                                                      \
        cp16(&As4[(s)*ST4 + ra *SLD + ca ], A  + (size_t)ra *LL + (k0) + ca );        \
        cp16(&As4[(s)*ST4 + rab*SLD + cab], A  + (size_t)rab*LL + (k0) + cab);        \
        cp16(&Bs4[(s)*ST4 + ra *SLD + ca ], Bg + (size_t)ra *LL + (k0) + ca );        \
        cp16(&Bs4[(s)*ST4 + rab*SLD + cab], Bg + (size_t)rab*LL + (k0) + cab);        \
        CP_COMMIT;                                                                    \
    } while (0)

    const int NIT = LL / BK4;
    K4_ISSUE(0, 0);
    K4_ISSUE(1, BK4);
    for (int it = 0; it < NIT; ++it) {
        if (it + 1 < NIT) { CP_WAIT1; } else { CP_WAIT0; }
        __syncthreads();
        if (it + 2 < NIT) K4_ISSUE((it + 2) % 3, (it + 2) * BK4);
        const uint32_t aB = aSm + (it % 3) * (ST4 * 2);
        const uint32_t bB = bSm + (it % 3) * (ST4 * 2);
        #pragma unroll
        for (int kk = 0; kk < 2; kk++) {
            uint32_t af[2][4];
            ldsm4(af[0], aB + offA[0] + kk*32);
            ldsm4(af[1], aB + offA[1] + kk*32);
            uint32_t bf[4][4];
            #pragma unroll
            for (int p = 0; p < 4; p++) ldsm4(bf[p], bB + offB[p] + kk*32);
            #pragma unroll
            for (int m = 0; m < 2; m++)
                #pragma unroll
                for (int n = 0; n < 8; n++)
                    mma_f16(acc[m][n], af[m], bf[n>>1][n&1], bf[n>>1][(n&1)+2]);
        }
    }
    #undef K4_ISSUE
    #pragma unroll
    for (int m = 0; m < 2; m++)
        #pragma unroll
        for (int rr = 0; rr < 2; rr++) {
            int row = row0 + wm + m*16 + qr + rr*8;
            float rinv = 1.f / g_R[b*LL + row];
            #pragma unroll
            for (int n = 0; n < 8; n++) {
                int col = col0 + wn + n*8 + 2*qc;
                float2 v;
                v.x = acc[m][n][rr*2+0] * rinv;
                v.y = acc[m][n][rr*2+1] * rinv;
                *(float2*)&out[((size_t)b*LL + row)*YD + col] = v;
            }
        }
}

// ============================================================
// K5a/K5b: temp_Qins two-stage mean (from fp16 Q)
// ============================================================
__global__ __launch_bounds__(256) void k5a() {
    const int b = blockIdx.x, lc = blockIdx.y;
    const int t = threadIdx.x;
    const int q = t & 63, part = t >> 6;
    float s = 0.f;
    #pragma unroll
    for (int d = 0; d < ND; d++) {
        const __half* base = g_Qh + (((size_t)d*BB + b)*LL + lc*128) * QDIM;
        for (int l = part; l < 128; l += 4) s += __half2float(base[(size_t)l * QDIM + q]);
    }
    __shared__ float red[256];
    red[t] = s;
    __syncthreads();
    if (part == 0)
        g_TQp[(b*8 + lc)*QDIM + q] = red[q] + red[64+q] + red[128+q] + red[192+q];
}
__global__ void k5b(float* __restrict__ out2) {
    const int b = blockIdx.x, q = threadIdx.x;
    float s = 0.f;
    #pragma unroll
    for (int lc = 0; lc < 8; lc++) s += g_TQp[(b*8 + lc)*QDIM + q];
    out2[b*QDIM + q] = s * (1.f / (ND * (float)LL));
}

// ============================================================
extern "C" void kernel_launch(void* const* d_in, const int* in_sizes, int n_in,
                              void* d_out, int out_size) {
    const float* X    = (const float*)d_in[0];
    const float* mask = (const float*)d_in[1];
    const float* Wq   = (const float*)d_in[2];
    const float* bq   = (const float*)d_in[3];
    const float* Wh   = (const float*)d_in[4];
    const float* bh   = (const float*)d_in[5];
    const float* Ws   = (const float*)d_in[6];
    const float* bs   = (const float*)d_in[7];
    float* out = (float*)d_out;

    float* gX; cudaGetSymbolAddress((void**)&gX, g_X);

    cudaFuncSetAttribute(k3_logits, cudaFuncAttributeMaxDynamicSharedMemorySize, K3_SMEM);
    cudaFuncSetAttribute(k4_pv,     cudaFuncAttributeMaxDynamicSharedMemorySize, K4_SMEM);

    kround<<<MTOT*XD/1024, 256>>>(X, gX, MTOT*XD);
    kprep<<<272, 256>>>(Wq, Wh, Ws);
    k1_qproj<<<dim3(2, 128), 256>>>(bq);
    k2a_h<<<dim3(1, 128), 256>>>(bh);
    k2b_sin<<<dim3(4, 128), 256>>>(bs);
    k3_logits<<<dim3(16, 8, 16), 256, K3_SMEM>>>(mask);
    k4_pv<<<dim3(4, 8, 16), 256, K4_SMEM>>>(out);
    k5a<<<dim3(16, 8), 256>>>();
    k5b<<<16, 64>>>(out + (size_t)BB * LL * YD);
}

// round 13
// speedup vs baseline: 4.1524x; 1.2560x over previous
#include <cuda_runtime.h>
#include <cuda_fp16.h>
#include <cstdint>

#define LL 1024
#define BB 16
#define XD 512
#define YD 512
#define QDIM 64
#define ND 4
#define HL 128
#define MTOT (LL*BB)
#define RSQRT512 0.04419417382415922f

// -------- scratch (device globals; no allocation allowed) --------
__device__ __half g_Xh [MTOT*XD];             // fp16 X
__device__ __half g_Wqh[ND*QDIM*XD];
__device__ __half g_Whh[HL*XD];
__device__ __half g_Wsh[YD*HL];
__device__ __half g_Qh [ND*BB*LL*QDIM];       // [d][b][l][q]
__device__ float  g_sq [ND*BB*LL];
__device__ __half g_hh [MTOT*HL];
__device__ __half g_SinT[(size_t)BB*YD*LL];   // [b][y][l]
__device__ __half g_E  [(size_t)BB*LL*LL];    // [b][i][j]
__device__ float  g_R  [BB*LL];
__device__ float  g_TQp[BB*8*QDIM];

__device__ __forceinline__ void cp16(void* dst, const void* src) {
    uint32_t d = (uint32_t)__cvta_generic_to_shared(dst);
    asm volatile("cp.async.cg.shared.global [%0], [%1], 16;" :: "r"(d), "l"(src));
}
#define CP_COMMIT asm volatile("cp.async.commit_group;")
#define CP_WAIT0  asm volatile("cp.async.wait_group 0;")
#define CP_WAIT1  asm volatile("cp.async.wait_group 1;")

__device__ __forceinline__ float sqrt_ap(float f) {
    float r; asm("sqrt.approx.f32 %0, %1;" : "=f"(r) : "f"(f)); return r;
}
__device__ __forceinline__ void ldsm4(uint32_t r[4], uint32_t addr) {
    asm volatile("ldmatrix.sync.aligned.m8n8.x4.shared.b16 {%0,%1,%2,%3}, [%4];"
        : "=r"(r[0]), "=r"(r[1]), "=r"(r[2]), "=r"(r[3]) : "r"(addr));
}
__device__ __forceinline__ void mma_f16(float c[4], const uint32_t a[4],
                                        uint32_t b0, uint32_t b1) {
    asm volatile("mma.sync.aligned.m16n8k16.row.col.f32.f16.f16.f32 "
        "{%0,%1,%2,%3}, {%4,%5,%6,%7}, {%8,%9}, {%0,%1,%2,%3};"
        : "+f"(c[0]), "+f"(c[1]), "+f"(c[2]), "+f"(c[3])
        : "r"(a[0]), "r"(a[1]), "r"(a[2]), "r"(a[3]), "r"(b0), "r"(b1));
}

// ---------------- unified fp16 BT GEMM mainloop ----------------
// A: [128 rows][K] halves (lda); Bg: [128 rows][K] halves (ldb) — both row-major
// 128x128 CTA tile, K-chunks of 64 halves (128B rows, XOR swizzle), 3-stage cp.async.
// Warp tile 32(m) x 64(n). acc[m 2][n-octet 8][4].
#define F16_STAGE 32768
template<int NCH>
__device__ __forceinline__ void gemm_f16(const __half* __restrict__ A, int lda,
                                         const __half* __restrict__ Bg, int ldb,
                                         float acc[2][8][4], char* sm, uint32_t smU)
{
    const int tid = threadIdx.x;
    const int lane = tid & 31, warp = tid >> 5;
    const int wm = (warp & 3) * 32, wn = (warp >> 2) * 64;
    const int la7 = lane & 7, hi = (lane >> 4) & 1;

    #define GLD(s, k0) do {                                                          \
        char* st_ = sm + (s)*F16_STAGE;                                              \
        _Pragma("unroll")                                                            \
        for (int i_ = 0; i_ < 8; i_++) {                                             \
            int u_ = tid + i_*256;                                                   \
            if (u_ < 1024) {                                                         \
                int row_ = u_ >> 3, c_ = u_ & 7;                                     \
                cp16(st_ + row_*128 + ((c_ ^ (row_ & 7)) << 4),                      \
                     A + (size_t)row_*lda + (k0) + c_*8);                            \
            } else {                                                                 \
                int v_ = u_ - 1024;                                                  \
                int row_ = v_ >> 3, c_ = v_ & 7;                                     \
                cp16(st_ + 16384 + row_*128 + ((c_ ^ (row_ & 7)) << 4),              \
                     Bg + (size_t)row_*ldb + (k0) + c_*8);                           \
            }                                                                        \
        }                                                                            \
        CP_COMMIT;                                                                   \
    } while (0)

    GLD(0, 0);
    if (NCH > 1) GLD(1, 64);
    for (int t = 0; t < NCH; t++) {
        if (t + 1 < NCH) { CP_WAIT1; } else { CP_WAIT0; }
        __syncthreads();
        if (t + 2 < NCH) GLD((t + 2) % 3, (t + 2) * 64);
        const uint32_t aB = smU + (t % 3) * F16_STAGE;
        const uint32_t bB = aB + 16384;
        #pragma unroll
        for (int kk = 0; kk < 4; kk++) {
            uint32_t af[2][4];
            #pragma unroll
            for (int m = 0; m < 2; m++) {
                int row = wm + m*16 + (lane & 15);
                ldsm4(af[m], aB + row*128 + (((kk*2 + hi) ^ (row & 7)) << 4));
            }
            uint32_t bf[4][4];
            #pragma unroll
            for (int p = 0; p < 4; p++) {
                int row = wn + p*16 + la7 + (lane & 8);
                ldsm4(bf[p], bB + row*128 + (((kk*2 + hi) ^ (row & 7)) << 4));
            }
            #pragma unroll
            for (int m = 0; m < 2; m++)
                #pragma unroll
                for (int n = 0; n < 8; n++)
                    mma_f16(acc[m][n], af[m], bf[n>>1][n&1], bf[n>>1][(n&1)+2]);
        }
    }
    #undef GLD
}
#define F16_SMEM (3*F16_STAGE)

// ============================================================
// kroundh: fp32 -> fp16 bulk convert;  kprep: weights + R-zero
// ============================================================
__global__ void kroundh(const float* __restrict__ src, __half* __restrict__ dst, int n) {
    int i = (blockIdx.x * 256 + threadIdx.x) * 4;
    if (i < n) {
        float4 v = *(const float4*)(src + i);
        *(__half2*)(dst + i)     = __floats2half2_rn(v.x, v.y);
        *(__half2*)(dst + i + 2) = __floats2half2_rn(v.z, v.w);
    }
}
__global__ void kprep(const float* __restrict__ Wq, const float* __restrict__ Wh,
                      const float* __restrict__ Ws) {
    int i = (blockIdx.x * 256 + threadIdx.x) * 4;
    const float* s; __half* d; int j;
    if (i < 131072)      { s = Wq; d = g_Wqh; j = i; }
    else if (i < 196608) { s = Wh; d = g_Whh; j = i - 131072; }
    else if (i < 262144) { s = Ws; d = g_Wsh; j = i - 196608; }
    else if (i < 278528) { j = i - 262144; *(float4*)&g_R[j] = make_float4(0,0,0,0); return; }
    else return;
    float4 v = *(const float4*)(s + j);
    *(__half2*)(d + j)     = __floats2half2_rn(v.x, v.y);
    *(__half2*)(d + j + 2) = __floats2half2_rn(v.z, v.w);
}

// ============================================================
// K1F: fused Q-proj (x=0,1) and h (x=2).  A = Xh[row0..], K=512
// ============================================================
__global__ __launch_bounds__(256, 2) void k1f(const float* __restrict__ bq,
                                              const float* __restrict__ bh) {
    extern __shared__ char sm[];
    const uint32_t smU = (uint32_t)__cvta_generic_to_shared(sm);
    const int x = blockIdx.x, row0 = blockIdx.y * 128;
    const __half* A  = g_Xh + (size_t)row0 * XD;
    const __half* Bg = (x < 2) ? g_Wqh + (size_t)x * 128 * XD : g_Whh;
    float acc[2][8][4] = {};
    gemm_f16<XD/64>(A, XD, Bg, XD, acc, sm, smU);
    const int lane = threadIdx.x & 31, warp = threadIdx.x >> 5;
    const int wm = (warp & 3) * 32, wn = (warp >> 2) * 64;
    const int qr = lane >> 2, qc = lane & 3;
    if (x < 2) {
        const int col0 = x * 128;
        const int d = (col0 + wn) >> 6;
        #pragma unroll
        for (int m = 0; m < 2; m++)
            #pragma unroll
            for (int rr = 0; rr < 2; rr++) {
                int mrow = row0 + wm + m*16 + qr + rr*8;
                int l = mrow >> 4, b = mrow & 15;
                float s = 0.f;
                #pragma unroll
                for (int n = 0; n < 8; n++) {
                    int cg = col0 + wn + n*8 + 2*qc;
                    int q = cg & 63;
                    __half2 hv = __floats2half2_rn(acc[m][n][rr*2+0] + bq[cg],
                                                   acc[m][n][rr*2+1] + bq[cg+1]);
                    float vx = __half2float(__low2half(hv));
                    float vy = __half2float(__high2half(hv));
                    s += vx*vx + vy*vy;
                    *(__half2*)&g_Qh[(((size_t)d*BB + b)*LL + l)*QDIM + q] = hv;
                }
                s += __shfl_xor_sync(0xffffffffu, s, 1);
                s += __shfl_xor_sync(0xffffffffu, s, 2);
                if (qc == 0) g_sq[((size_t)d*BB + b)*LL + l] = s;
            }
    } else {
        #pragma unroll
        for (int m = 0; m < 2; m++)
            #pragma unroll
            for (int rr = 0; rr < 2; rr++) {
                int mrow = row0 + wm + m*16 + qr + rr*8;
                #pragma unroll
                for (int n = 0; n < 8; n++) {
                    int cg = wn + n*8 + 2*qc;
                    float v0 = 1.f / (1.f + __expf(-(acc[m][n][rr*2+0] + bh[cg])));
                    float v1 = 1.f / (1.f + __expf(-(acc[m][n][rr*2+1] + bh[cg+1])));
                    *(__half2*)&g_hh[(size_t)mrow * HL + cg] = __floats2half2_rn(v0, v1);
                }
            }
    }
}

// ============================================================
// K2b: Sin = h @ Ws^T + bs -> g_SinT[b][y][l]  (fp16, transposed), K=128
// ============================================================
__global__ __launch_bounds__(256, 2) void k2b_sin(const float* __restrict__ bs) {
    extern __shared__ char sm[];
    const uint32_t smU = (uint32_t)__cvta_generic_to_shared(sm);
    const int row0 = blockIdx.y * 128, col0 = blockIdx.x * 128;
    float acc[2][8][4] = {};
    gemm_f16<HL/64>(g_hh + (size_t)row0 * HL, HL, g_Wsh + (size_t)col0 * HL, HL, acc, sm, smU);
    const int lane = threadIdx.x & 31, warp = threadIdx.x >> 5;
    const int wm = (warp & 3) * 32, wn = (warp >> 2) * 64;
    const int qr = lane >> 2, qc = lane & 3;
    #pragma unroll
    for (int m = 0; m < 2; m++)
        #pragma unroll
        for (int rr = 0; rr < 2; rr++) {
            int mrow = row0 + wm + m*16 + qr + rr*8;
            int l = mrow >> 4, b = mrow & 15;
            #pragma unroll
            for (int n = 0; n < 8; n++) {
                int cg = col0 + wn + n*8 + 2*qc;
                g_SinT[((size_t)b*YD + cg  )*LL + l] = __float2half(acc[m][n][rr*2+0] + bs[cg]);
                g_SinT[((size_t)b*YD + cg+1)*LL + l] = __float2half(acc[m][n][rr*2+1] + bs[cg+1]);
            }
        }
}

// ============================================================
// K3: fp16 Gram -> logits -> E (fp16), fused rowsum (unchanged from r12)
// ============================================================
#define K3_STAGE 24576
#define K3_SMEM  (3*K3_STAGE)
__global__ __launch_bounds__(256, 2) void k3_logits(const float* __restrict__ mask) {
    extern __shared__ char sm3[];
    const int bI = blockIdx.z;
    const int i0 = blockIdx.y * 128, j0 = blockIdx.x * 64;
    const int tid = threadIdx.x;
    const int lane = tid & 31, warp = tid >> 5;
    const int wm = (warp & 3) * 32, wn = (warp >> 2) * 32;
    const int qr = lane >> 2, qc = lane & 3;
    const uint32_t smU = (uint32_t)__cvta_generic_to_shared(sm3);

    #define K3_LD(s, d_) do {                                                        \
        const __half* Ab_ = g_Qh + (((size_t)(d_)*BB + bI)*LL + i0) * QDIM;          \
        const __half* Bb_ = g_Qh + (((size_t)(d_)*BB + bI)*LL + j0) * QDIM;          \
        char* st_ = sm3 + (s)*K3_STAGE;                                              \
        _Pragma("unroll")                                                            \
        for (int i_ = 0; i_ < 6; i_++) {                                             \
            int u_ = tid + i_*256;                                                   \
            if (u_ < 1024) {                                                         \
                int row_ = u_ >> 3, c_ = u_ & 7;                                     \
                cp16(st_ + row_*128 + ((c_ ^ (row_ & 7)) << 4),                      \
                     Ab_ + (size_t)row_*QDIM + c_*8);                                \
            } else {                                                                 \
                int v_ = u_ - 1024;                                                  \
                int row_ = v_ >> 3, c_ = v_ & 7;                                     \
                cp16(st_ + 16384 + row_*128 + ((c_ ^ (row_ & 7)) << 4),              \
                     Bb_ + (size_t)row_*QDIM + c_*8);                                \
            }                                                                        \
        }                                                                            \
        CP_COMMIT;                                                                   \
    } while (0)

    float logit[2][4][4] = {};
    K3_LD(0, 0);
    K3_LD(1, 1);
    const int la7 = lane & 7, hi = (lane >> 4) & 1;
    for (int d = 0; d < ND; d++) {
        if (d + 1 < ND) { CP_WAIT1; } else { CP_WAIT0; }
        __syncthreads();
        if (d + 2 < ND) K3_LD((d + 2) % 3, d + 2);
        const uint32_t aB = smU + (d % 3) * K3_STAGE;
        const uint32_t bB = aB + 16384;
        float acc[2][4][4] = {};
        #pragma unroll
        for (int kk = 0; kk < 4; kk++) {
            int sw = ((kk*2 + hi) ^ la7) << 4;
            uint32_t af[2][4];
            #pragma unroll
            for (int m = 0; m < 2; m++) {
                int row = wm + m*16 + (lane & 15);
                ldsm4(af[m], aB + row*128 + (((kk*2 + hi) ^ (row & 7)) << 4));
            }
            uint32_t bf[2][4];
            #pragma unroll
            for (int p = 0; p < 2; p++) {
                int row = wn + p*16 + la7 + (lane & 8);
                ldsm4(bf[p], bB + row*128 + sw);
            }
            #pragma unroll
            for (int m = 0; m < 2; m++)
                #pragma unroll
                for (int n = 0; n < 4; n++)
                    mma_f16(acc[m][n], af[m], bf[n>>1][n&1], bf[n>>1][(n&1)+2]);
        }
        const float sgn = (d & 1) ? -1.f : 1.f;
        const float* sqb = g_sq + ((size_t)d*BB + bI) * LL;
        #pragma unroll
        for (int m = 0; m < 2; m++)
            #pragma unroll
            for (int rr = 0; rr < 2; rr++) {
                int gi = i0 + wm + m*16 + qr + rr*8;
                float sqi = sqb[gi];
                #pragma unroll
                for (int n = 0; n < 4; n++) {
                    int gj = j0 + wn + n*8 + 2*qc;
                    float d20 = fmaxf(sqi + sqb[gj]   - 2.f*acc[m][n][rr*2+0], 0.f);
                    float d21 = fmaxf(sqi + sqb[gj+1] - 2.f*acc[m][n][rr*2+1], 0.f);
                    logit[m][n][rr*2+0] += (gi == gj)   ? 0.f : sgn * sqrt_ap(d20);
                    logit[m][n][rr*2+1] += (gi == gj+1) ? 0.f : sgn * sqrt_ap(d21);
                }
            }
    }
    #undef K3_LD
    #pragma unroll
    for (int m = 0; m < 2; m++)
        #pragma unroll
        for (int rr = 0; rr < 2; rr++) {
            int gi = i0 + wm + m*16 + qr + rr*8;
            float s = 0.f;
            #pragma unroll
            for (int n = 0; n < 4; n++) {
                int gj = j0 + wn + n*8 + 2*qc;
                float2 mv = *(const float2*)&mask[(size_t)gi * LL + gj];
                float e0 = __expf(logit[m][n][rr*2+0] * RSQRT512 + mv.x);
                float e1 = __expf(logit[m][n][rr*2+1] * RSQRT512 + mv.y);
                __half2 p2 = __floats2half2_rn(e0, e1);
                s += __half2float(__low2half(p2)) + __half2float(__high2half(p2));
                *(__half2*)&g_E[((size_t)bI*LL + gi)*LL + gj] = p2;
            }
            s += __shfl_xor_sync(0xffffffffu, s, 1);
            s += __shfl_xor_sync(0xffffffffu, s, 2);
            if (qc == 0) atomicAdd(&g_R[bI*LL + gi], s);
        }
}

// ============================================================
// K4: Sout[b] = diag(1/R) * E[b] @ SinT[b]^T  — unified fp16 GEMM, K=1024
// ============================================================
__global__ __launch_bounds__(256, 2) void k4_pv(float* __restrict__ out) {
    extern __shared__ char sm[];
    const uint32_t smU = (uint32_t)__cvta_generic_to_shared(sm);
    const int b = blockIdx.z;
    const int row0 = blockIdx.y * 128, col0 = blockIdx.x * 128;
    float acc[2][8][4] = {};
    gemm_f16<LL/64>(g_E + (size_t)b*LL*LL + (size_t)row0*LL, LL,
                    g_SinT + ((size_t)b*YD + col0)*LL, LL, acc, sm, smU);
    const int lane = threadIdx.x & 31, warp = threadIdx.x >> 5;
    const int wm = (warp & 3) * 32, wn = (warp >> 2) * 64;
    const int qr = lane >> 2, qc = lane & 3;
    #pragma unroll
    for (int m = 0; m < 2; m++)
        #pragma unroll
        for (int rr = 0; rr < 2; rr++) {
            int row = row0 + wm + m*16 + qr + rr*8;
            float rinv = 1.f / g_R[b*LL + row];
            #pragma unroll
            for (int n = 0; n < 8; n++) {
                int col = col0 + wn + n*8 + 2*qc;
                float2 v;
                v.x = acc[m][n][rr*2+0] * rinv;
                v.y = acc[m][n][rr*2+1] * rinv;
                *(float2*)&out[((size_t)b*LL + row)*YD + col] = v;
            }
        }
}

// ============================================================
// K5a/K5b: temp_Qins two-stage mean (from fp16 Q)
// ============================================================
__global__ __launch_bounds__(256) void k5a() {
    const int b = blockIdx.x, lc = blockIdx.y;
    const int t = threadIdx.x;
    const int q = t & 63, part = t >> 6;
    float s = 0.f;
    #pragma unroll
    for (int d = 0; d < ND; d++) {
        const __half* base = g_Qh + (((size_t)d*BB + b)*LL + lc*128) * QDIM;
        for (int l = part; l < 128; l += 4) s += __half2float(base[(size_t)l * QDIM + q]);
    }
    __shared__ float red[256];
    red[t] = s;
    __syncthreads();
    if (part == 0)
        g_TQp[(b*8 + lc)*QDIM + q] = red[q] + red[64+q] + red[128+q] + red[192+q];
}
__global__ void k5b(float* __restrict__ out2) {
    const int b = blockIdx.x, q = threadIdx.x;
    float s = 0.f;
    #pragma unroll
    for (int lc = 0; lc < 8; lc++) s += g_TQp[(b*8 + lc)*QDIM + q];
    out2[b*QDIM + q] = s * (1.f / (ND * (float)LL));
}

// ============================================================
extern "C" void kernel_launch(void* const* d_in, const int* in_sizes, int n_in,
                              void* d_out, int out_size) {
    const float* X    = (const float*)d_in[0];
    const float* mask = (const float*)d_in[1];
    const float* Wq   = (const float*)d_in[2];
    const float* bq   = (const float*)d_in[3];
    const float* Wh   = (const float*)d_in[4];
    const float* bh   = (const float*)d_in[5];
    const float* Ws   = (const float*)d_in[6];
    const float* bs   = (const float*)d_in[7];
    float* out = (float*)d_out;

    __half* gXh; cudaGetSymbolAddress((void**)&gXh, g_Xh);

    cudaFuncSetAttribute(k1f,       cudaFuncAttributeMaxDynamicSharedMemorySize, F16_SMEM);
    cudaFuncSetAttribute(k2b_sin,   cudaFuncAttributeMaxDynamicSharedMemorySize, F16_SMEM);
    cudaFuncSetAttribute(k3_logits, cudaFuncAttributeMaxDynamicSharedMemorySize, K3_SMEM);
    cudaFuncSetAttribute(k4_pv,     cudaFuncAttributeMaxDynamicSharedMemorySize, F16_SMEM);

    kroundh<<<MTOT*XD/1024, 256>>>(X, gXh, MTOT*XD);
    kprep<<<272, 256>>>(Wq, Wh, Ws);
    k1f<<<dim3(3, 128), 256, F16_SMEM>>>(bq, bh);
    k2b_sin<<<dim3(4, 128), 256, F16_SMEM>>>(bs);
    k3_logits<<<dim3(16, 8, 16), 256, K3_SMEM>>>(mask);
    k4_pv<<<dim3(4, 8, 16), 256, F16_SMEM>>>(out);
    k5a<<<dim3(16, 8), 256>>>();
    k5b<<<16, 64>>>(out + (size_t)BB * LL * YD);
}

// round 14
// speedup vs baseline: 5.5252x; 1.3306x over previous
#include <cuda_runtime.h>
#include <cuda_fp16.h>
#include <cstdint>

#define LL 1024
#define BB 16
#define XD 512
#define YD 512
#define QDIM 64
#define ND 4
#define HL 128
#define MTOT (LL*BB)
#define RSQRT512 0.04419417382415922f

// -------- scratch (device globals; no allocation allowed) --------
__device__ __half g_Xh [MTOT*XD];             // fp16 X
__device__ __half g_Wqh[ND*QDIM*XD];
__device__ __half g_Whh[HL*XD];
__device__ __half g_Wsh[YD*HL];
__device__ __half g_Qh [ND*BB*LL*QDIM];       // [d][b][l][q]
__device__ float  g_sq [ND*BB*LL];
__device__ __half g_hh [MTOT*HL];
__device__ __half g_SinT[(size_t)BB*YD*LL];   // [b][y][l]
__device__ __half g_E  [(size_t)BB*LL*LL];    // [b][i][j]
__device__ float  g_R  [BB*LL];
__device__ float  g_TQp[BB*8*QDIM];

__device__ __forceinline__ void cp16(void* dst, const void* src) {
    uint32_t d = (uint32_t)__cvta_generic_to_shared(dst);
    asm volatile("cp.async.cg.shared.global [%0], [%1], 16;" :: "r"(d), "l"(src));
}
#define CP_COMMIT asm volatile("cp.async.commit_group;")
#define CP_WAIT0  asm volatile("cp.async.wait_group 0;")
#define CP_WAIT1  asm volatile("cp.async.wait_group 1;")

__device__ __forceinline__ float sqrt_ap(float f) {
    float r; asm("sqrt.approx.f32 %0, %1;" : "=f"(r) : "f"(f)); return r;
}
__device__ __forceinline__ void ldsm4(uint32_t r[4], uint32_t addr) {
    asm volatile("ldmatrix.sync.aligned.m8n8.x4.shared.b16 {%0,%1,%2,%3}, [%4];"
        : "=r"(r[0]), "=r"(r[1]), "=r"(r[2]), "=r"(r[3]) : "r"(addr));
}
__device__ __forceinline__ void mma_f16(float c[4], const uint32_t a[4],
                                        uint32_t b0, uint32_t b1) {
    asm volatile("mma.sync.aligned.m16n8k16.row.col.f32.f16.f16.f32 "
        "{%0,%1,%2,%3}, {%4,%5,%6,%7}, {%8,%9}, {%0,%1,%2,%3};"
        : "+f"(c[0]), "+f"(c[1]), "+f"(c[2]), "+f"(c[3])
        : "r"(a[0]), "r"(a[1]), "r"(a[2]), "r"(a[3]), "r"(b0), "r"(b1));
}

// ---------------- unified fp16 BT GEMM mainloop ----------------
#define F16_STAGE 32768
template<int NCH>
__device__ __forceinline__ void gemm_f16(const __half* __restrict__ A, int lda,
                                         const __half* __restrict__ Bg, int ldb,
                                         float acc[2][8][4], char* sm, uint32_t smU)
{
    const int tid = threadIdx.x;
    const int lane = tid & 31, warp = tid >> 5;
    const int wm = (warp & 3) * 32, wn = (warp >> 2) * 64;
    const int la7 = lane & 7, hi = (lane >> 4) & 1;

    #define GLD(s, k0) do {                                                          \
        char* st_ = sm + (s)*F16_STAGE;                                              \
        _Pragma("unroll")                                                            \
        for (int i_ = 0; i_ < 8; i_++) {                                             \
            int u_ = tid + i_*256;                                                   \
            if (u_ < 1024) {                                                         \
                int row_ = u_ >> 3, c_ = u_ & 7;                                     \
                cp16(st_ + row_*128 + ((c_ ^ (row_ & 7)) << 4),                      \
                     A + (size_t)row_*lda + (k0) + c_*8);                            \
            } else {                                                                 \
                int v_ = u_ - 1024;                                                  \
                int row_ = v_ >> 3, c_ = v_ & 7;                                     \
                cp16(st_ + 16384 + row_*128 + ((c_ ^ (row_ & 7)) << 4),              \
                     Bg + (size_t)row_*ldb + (k0) + c_*8);                           \
            }                                                                        \
        }                                                                            \
        CP_COMMIT;                                                                   \
    } while (0)

    GLD(0, 0);
    if (NCH > 1) GLD(1, 64);
    for (int t = 0; t < NCH; t++) {
        if (t + 1 < NCH) { CP_WAIT1; } else { CP_WAIT0; }
        __syncthreads();
        if (t + 2 < NCH) GLD((t + 2) % 3, (t + 2) * 64);
        const uint32_t aB = smU + (t % 3) * F16_STAGE;
        const uint32_t bB = aB + 16384;
        #pragma unroll
        for (int kk = 0; kk < 4; kk++) {
            uint32_t af[2][4];
            #pragma unroll
            for (int m = 0; m < 2; m++) {
                int row = wm + m*16 + (lane & 15);
                ldsm4(af[m], aB + row*128 + (((kk*2 + hi) ^ (row & 7)) << 4));
            }
            uint32_t bf[4][4];
            #pragma unroll
            for (int p = 0; p < 4; p++) {
                int row = wn + p*16 + la7 + (lane & 8);
                ldsm4(bf[p], bB + row*128 + (((kk*2 + hi) ^ (row & 7)) << 4));
            }
            #pragma unroll
            for (int m = 0; m < 2; m++)
                #pragma unroll
                for (int n = 0; n < 8; n++)
                    mma_f16(acc[m][n], af[m], bf[n>>1][n&1], bf[n>>1][(n&1)+2]);
        }
    }
    #undef GLD
}
#define F16_SMEM (3*F16_STAGE)

// ============================================================
// kroundh / kprep
// ============================================================
__global__ void kroundh(const float* __restrict__ src, __half* __restrict__ dst, int n) {
    int i = (blockIdx.x * 256 + threadIdx.x) * 4;
    if (i < n) {
        float4 v = *(const float4*)(src + i);
        *(__half2*)(dst + i)     = __floats2half2_rn(v.x, v.y);
        *(__half2*)(dst + i + 2) = __floats2half2_rn(v.z, v.w);
    }
}
__global__ void kprep(const float* __restrict__ Wq, const float* __restrict__ Wh,
                      const float* __restrict__ Ws) {
    int i = (blockIdx.x * 256 + threadIdx.x) * 4;
    const float* s; __half* d; int j;
    if (i < 131072)      { s = Wq; d = g_Wqh; j = i; }
    else if (i < 196608) { s = Wh; d = g_Whh; j = i - 131072; }
    else if (i < 262144) { s = Ws; d = g_Wsh; j = i - 196608; }
    else if (i < 278528) { j = i - 262144; *(float4*)&g_R[j] = make_float4(0,0,0,0); return; }
    else return;
    float4 v = *(const float4*)(s + j);
    *(__half2*)(d + j)     = __floats2half2_rn(v.x, v.y);
    *(__half2*)(d + j + 2) = __floats2half2_rn(v.z, v.w);
}

// ============================================================
// K1F: fused Q-proj (x=0,1) and h (x=2).  A = Xh[row0..], K=512
// ============================================================
__global__ __launch_bounds__(256, 2) void k1f(const float* __restrict__ bq,
                                              const float* __restrict__ bh) {
    extern __shared__ char sm[];
    const uint32_t smU = (uint32_t)__cvta_generic_to_shared(sm);
    const int x = blockIdx.x, row0 = blockIdx.y * 128;
    const __half* A  = g_Xh + (size_t)row0 * XD;
    const __half* Bg = (x < 2) ? g_Wqh + (size_t)x * 128 * XD : g_Whh;
    float acc[2][8][4] = {};
    gemm_f16<XD/64>(A, XD, Bg, XD, acc, sm, smU);
    const int lane = threadIdx.x & 31, warp = threadIdx.x >> 5;
    const int wm = (warp & 3) * 32, wn = (warp >> 2) * 64;
    const int qr = lane >> 2, qc = lane & 3;
    if (x < 2) {
        const int col0 = x * 128;
        const int d = (col0 + wn) >> 6;
        #pragma unroll
        for (int m = 0; m < 2; m++)
            #pragma unroll
            for (int rr = 0; rr < 2; rr++) {
                int mrow = row0 + wm + m*16 + qr + rr*8;
                int l = mrow >> 4, b = mrow & 15;
                float s = 0.f;
                #pragma unroll
                for (int n = 0; n < 8; n++) {
                    int cg = col0 + wn + n*8 + 2*qc;
                    int q = cg & 63;
                    __half2 hv = __floats2half2_rn(acc[m][n][rr*2+0] + bq[cg],
                                                   acc[m][n][rr*2+1] + bq[cg+1]);
                    float vx = __half2float(__low2half(hv));
                    float vy = __half2float(__high2half(hv));
                    s += vx*vx + vy*vy;
                    *(__half2*)&g_Qh[(((size_t)d*BB + b)*LL + l)*QDIM + q] = hv;
                }
                s += __shfl_xor_sync(0xffffffffu, s, 1);
                s += __shfl_xor_sync(0xffffffffu, s, 2);
                if (qc == 0) g_sq[((size_t)d*BB + b)*LL + l] = s;
            }
    } else {
        #pragma unroll
        for (int m = 0; m < 2; m++)
            #pragma unroll
            for (int rr = 0; rr < 2; rr++) {
                int mrow = row0 + wm + m*16 + qr + rr*8;
                #pragma unroll
                for (int n = 0; n < 8; n++) {
                    int cg = wn + n*8 + 2*qc;
                    float v0 = 1.f / (1.f + __expf(-(acc[m][n][rr*2+0] + bh[cg])));
                    float v1 = 1.f / (1.f + __expf(-(acc[m][n][rr*2+1] + bh[cg+1])));
                    *(__half2*)&g_hh[(size_t)mrow * HL + cg] = __floats2half2_rn(v0, v1);
                }
            }
    }
}

// ============================================================
// K2b: Sin = h @ Ws^T + bs -> g_SinT[b][y][l]  (fp16, smem-staged transpose)
// ============================================================
#define TLD 136
__global__ __launch_bounds__(256, 2) void k2b_sin(const float* __restrict__ bs) {
    extern __shared__ char sm[];
    const uint32_t smU = (uint32_t)__cvta_generic_to_shared(sm);
    const int row0 = blockIdx.y * 128, col0 = blockIdx.x * 128;
    float acc[2][8][4] = {};
    gemm_f16<HL/64>(g_hh + (size_t)row0 * HL, HL, g_Wsh + (size_t)col0 * HL, HL, acc, sm, smU);
    const int tid = threadIdx.x;
    const int lane = tid & 31, warp = tid >> 5;
    const int wm = (warp & 3) * 32, wn = (warp >> 2) * 64;
    const int qr = lane >> 2, qc = lane & 3;
    __syncthreads();                         // mainloop done with smem in all warps
    __half* T = (__half*)sm;                 // T[y 0..127][m 0..127], stride TLD
    #pragma unroll
    for (int m = 0; m < 2; m++)
        #pragma unroll
        for (int rr = 0; rr < 2; rr++) {
            int mr = wm + m*16 + qr + rr*8;  // 0..127
            #pragma unroll
            for (int n = 0; n < 8; n++) {
                int cc = wn + n*8 + 2*qc;    // 0..127
                T[cc*TLD + mr]     = __float2half(acc[m][n][rr*2+0] + bs[col0 + cc]);
                T[(cc+1)*TLD + mr] = __float2half(acc[m][n][rr*2+1] + bs[col0 + cc + 1]);
            }
        }
    __syncthreads();
    const int l0 = row0 >> 4;                // multiple of 8
    #pragma unroll
    for (int r = 0; r < 8; r++) {
        int idx = tid + r*256;               // 0..2047
        int b = idx & 15, y = idx >> 4;      // y 0..127
        __half tmp[8];
        #pragma unroll
        for (int lo = 0; lo < 8; lo++) tmp[lo] = T[y*TLD + lo*16 + b];
        *(uint4*)&g_SinT[((size_t)b*YD + col0 + y)*LL + l0] = *(uint4*)tmp;
    }
}

// ============================================================
// K3: fp16 Gram -> logits -> E (fp16), fused rowsum
// ============================================================
#define K3_STAGE 24576
#define K3_SMEM  (3*K3_STAGE)
__global__ __launch_bounds__(256, 2) void k3_logits(const float* __restrict__ mask) {
    extern __shared__ char sm3[];
    const int bI = blockIdx.z;
    const int i0 = blockIdx.y * 128, j0 = blockIdx.x * 64;
    const int tid = threadIdx.x;
    const int lane = tid & 31, warp = tid >> 5;
    const int wm = (warp & 3) * 32, wn = (warp >> 2) * 32;
    const int qr = lane >> 2, qc = lane & 3;
    const uint32_t smU = (uint32_t)__cvta_generic_to_shared(sm3);

    #define K3_LD(s, d_) do {                                                        \
        const __half* Ab_ = g_Qh + (((size_t)(d_)*BB + bI)*LL + i0) * QDIM;          \
        const __half* Bb_ = g_Qh + (((size_t)(d_)*BB + bI)*LL + j0) * QDIM;          \
        char* st_ = sm3 + (s)*K3_STAGE;                                              \
        _Pragma("unroll")                                                            \
        for (int i_ = 0; i_ < 6; i_++) {                                             \
            int u_ = tid + i_*256;                                                   \
            if (u_ < 1024) {                                                         \
                int row_ = u_ >> 3, c_ = u_ & 7;                                     \
                cp16(st_ + row_*128 + ((c_ ^ (row_ & 7)) << 4),                      \
                     Ab_ + (size_t)row_*QDIM + c_*8);                                \
            } else {                                                                 \
                int v_ = u_ - 1024;                                                  \
                int row_ = v_ >> 3, c_ = v_ & 7;                                     \
                cp16(st_ + 16384 + row_*128 + ((c_ ^ (row_ & 7)) << 4),              \
                     Bb_ + (size_t)row_*QDIM + c_*8);                                \
            }                                                                        \
        }                                                                            \
        CP_COMMIT;                                                                   \
    } while (0)

    float logit[2][4][4] = {};
    K3_LD(0, 0);
    K3_LD(1, 1);
    const int la7 = lane & 7, hi = (lane >> 4) & 1;
    for (int d = 0; d < ND; d++) {
        if (d + 1 < ND) { CP_WAIT1; } else { CP_WAIT0; }
        __syncthreads();
        if (d + 2 < ND) K3_LD((d + 2) % 3, d + 2);
        const uint32_t aB = smU + (d % 3) * K3_STAGE;
        const uint32_t bB = aB + 16384;
        float acc[2][4][4] = {};
        #pragma unroll
        for (int kk = 0; kk < 4; kk++) {
            int sw = ((kk*2 + hi) ^ la7) << 4;
            uint32_t af[2][4];
            #pragma unroll
            for (int m = 0; m < 2; m++) {
                int row = wm + m*16 + (lane & 15);
                ldsm4(af[m], aB + row*128 + (((kk*2 + hi) ^ (row & 7)) << 4));
            }
            uint32_t bf[2][4];
            #pragma unroll
            for (int p = 0; p < 2; p++) {
                int row = wn + p*16 + la7 + (lane & 8);
                ldsm4(bf[p], bB + row*128 + sw);
            }
            #pragma unroll
            for (int m = 0; m < 2; m++)
                #pragma unroll
                for (int n = 0; n < 4; n++)
                    mma_f16(acc[m][n], af[m], bf[n>>1][n&1], bf[n>>1][(n&1)+2]);
        }
        const float sgn = (d & 1) ? -1.f : 1.f;
        const float* sqb = g_sq + ((size_t)d*BB + bI) * LL;
        #pragma unroll
        for (int m = 0; m < 2; m++)
            #pragma unroll
            for (int rr = 0; rr < 2; rr++) {
                int gi = i0 + wm + m*16 + qr + rr*8;
                float sqi = sqb[gi];
                #pragma unroll
                for (int n = 0; n < 4; n++) {
                    int gj = j0 + wn + n*8 + 2*qc;
                    float d20 = fmaxf(sqi + sqb[gj]   - 2.f*acc[m][n][rr*2+0], 0.f);
                    float d21 = fmaxf(sqi + sqb[gj+1] - 2.f*acc[m][n][rr*2+1], 0.f);
                    logit[m][n][rr*2+0] += (gi == gj)   ? 0.f : sgn * sqrt_ap(d20);
                    logit[m][n][rr*2+1] += (gi == gj+1) ? 0.f : sgn * sqrt_ap(d21);
                }
            }
    }
    #undef K3_LD
    #pragma unroll
    for (int m = 0; m < 2; m++)
        #pragma unroll
        for (int rr = 0; rr < 2; rr++) {
            int gi = i0 + wm + m*16 + qr + rr*8;
            float s = 0.f;
            #pragma unroll
            for (int n = 0; n < 4; n++) {
                int gj = j0 + wn + n*8 + 2*qc;
                float2 mv = *(const float2*)&mask[(size_t)gi * LL + gj];
                float e0 = __expf(logit[m][n][rr*2+0] * RSQRT512 + mv.x);
                float e1 = __expf(logit[m][n][rr*2+1] * RSQRT512 + mv.y);
                __half2 p2 = __floats2half2_rn(e0, e1);
                s += __half2float(__low2half(p2)) + __half2float(__high2half(p2));
                *(__half2*)&g_E[((size_t)bI*LL + gi)*LL + gj] = p2;
            }
            s += __shfl_xor_sync(0xffffffffu, s, 1);
            s += __shfl_xor_sync(0xffffffffu, s, 2);
            if (qc == 0) atomicAdd(&g_R[bI*LL + gi], s);
        }
}

// ============================================================
// K4: Sout[b] = diag(1/R) * E[b] @ SinT[b]^T  — unified fp16 GEMM, K=1024
// ============================================================
__global__ __launch_bounds__(256, 2) void k4_pv(float* __restrict__ out) {
    extern __shared__ char sm[];
    const uint32_t smU = (uint32_t)__cvta_generic_to_shared(sm);
    const int b = blockIdx.z;
    const int row0 = blockIdx.y * 128, col0 = blockIdx.x * 128;
    float acc[2][8][4] = {};
    gemm_f16<LL/64>(g_E + (size_t)b*LL*LL + (size_t)row0*LL, LL,
                    g_SinT + ((size_t)b*YD + col0)*LL, LL, acc, sm, smU);
    const int lane = threadIdx.x & 31, warp = threadIdx.x >> 5;
    const int wm = (warp & 3) * 32, wn = (warp >> 2) * 64;
    const int qr = lane >> 2, qc = lane & 3;
    #pragma unroll
    for (int m = 0; m < 2; m++)
        #pragma unroll
        for (int rr = 0; rr < 2; rr++) {
            int row = row0 + wm + m*16 + qr + rr*8;
            float rinv = 1.f / g_R[b*LL + row];
            #pragma unroll
            for (int n = 0; n < 8; n++) {
                int col = col0 + wn + n*8 + 2*qc;
                float2 v;
                v.x = acc[m][n][rr*2+0] * rinv;
                v.y = acc[m][n][rr*2+1] * rinv;
                *(float2*)&out[((size_t)b*LL + row)*YD + col] = v;
            }
        }
}

// ============================================================
// K5a/K5b: temp_Qins two-stage mean (from fp16 Q)
// ============================================================
__global__ __launch_bounds__(256) void k5a() {
    const int b = blockIdx.x, lc = blockIdx.y;
    const int t = threadIdx.x;
    const int q = t & 63, part = t >> 6;
    float s = 0.f;
    #pragma unroll
    for (int d = 0; d < ND; d++) {
        const __half* base = g_Qh + (((size_t)d*BB + b)*LL + lc*128) * QDIM;
        for (int l = part; l < 128; l += 4) s += __half2float(base[(size_t)l * QDIM + q]);
    }
    __shared__ float red[256];
    red[t] = s;
    __syncthreads();
    if (part == 0)
        g_TQp[(b*8 + lc)*QDIM + q] = red[q] + red[64+q] + red[128+q] + red[192+q];
}
__global__ void k5b(float* __restrict__ out2) {
    const int b = blockIdx.x, q = threadIdx.x;
    float s = 0.f;
    #pragma unroll
    for (int lc = 0; lc < 8; lc++) s += g_TQp[(b*8 + lc)*QDIM + q];
    out2[b*QDIM + q] = s * (1.f / (ND * (float)LL));
}

// ============================================================
extern "C" void kernel_launch(void* const* d_in, const int* in_sizes, int n_in,
                              void* d_out, int out_size) {
    const float* X    = (const float*)d_in[0];
    const float* mask = (const float*)d_in[1];
    const float* Wq   = (const float*)d_in[2];
    const float* bq   = (const float*)d_in[3];
    const float* Wh   = (const float*)d_in[4];
    const float* bh   = (const float*)d_in[5];
    const float* Ws   = (const float*)d_in[6];
    const float* bs   = (const float*)d_in[7];
    float* out = (float*)d_out;

    __half* gXh; cudaGetSymbolAddress((void**)&gXh, g_Xh);

    cudaFuncSetAttribute(k1f,       cudaFuncAttributeMaxDynamicSharedMemorySize, F16_SMEM);
    cudaFuncSetAttribute(k2b_sin,   cudaFuncAttributeMaxDynamicSharedMemorySize, F16_SMEM);
    cudaFuncSetAttribute(k3_logits, cudaFuncAttributeMaxDynamicSharedMemorySize, K3_SMEM);
    cudaFuncSetAttribute(k4_pv,     cudaFuncAttributeMaxDynamicSharedMemorySize, F16_SMEM);

    kroundh<<<MTOT*XD/1024, 256>>>(X, gXh, MTOT*XD);
    kprep<<<272, 256>>>(Wq, Wh, Ws);
    k1f<<<dim3(3, 128), 256, F16_SMEM>>>(bq, bh);
    k2b_sin<<<dim3(4, 128), 256, F16_SMEM>>>(bs);
    k3_logits<<<dim3(16, 8, 16), 256, K3_SMEM>>>(mask);
    k4_pv<<<dim3(4, 8, 16), 256, F16_SMEM>>>(out);
    k5a<<<dim3(16, 8), 256>>>();
    k5b<<<16, 64>>>(out + (size_t)BB * LL * YD);
}

// round 15
// speedup vs baseline: 6.3903x; 1.1566x over previous
#include <cuda_runtime.h>
#include <cuda_fp16.h>
#include <cstdint>

#define LL 1024
#define BB 16
#define XD 512
#define YD 512
#define QDIM 64
#define ND 4
#define HL 128
#define MTOT (LL*BB)
#define RSQRT512 0.04419417382415922f

// -------- scratch (device globals; no allocation allowed) --------
__device__ __half g_Xh [MTOT*XD];
__device__ __half g_Wqh[ND*QDIM*XD];
__device__ __half g_Whh[HL*XD];
__device__ __half g_Wsh[YD*HL];
__device__ __half g_Qh [ND*BB*LL*QDIM];       // [d][b][l][q]
__device__ float  g_sq [ND*BB*LL];
__device__ __half g_hh [MTOT*HL];
__device__ __half g_SinT[(size_t)BB*YD*LL];   // [b][y][l]
__device__ __half g_E  [(size_t)BB*LL*LL];    // [b][i][j]
__device__ float  g_R  [BB*LL];
__device__ float  g_TQp[BB*8*QDIM];

__device__ __forceinline__ void cp16(void* dst, const void* src) {
    uint32_t d = (uint32_t)__cvta_generic_to_shared(dst);
    asm volatile("cp.async.cg.shared.global [%0], [%1], 16;" :: "r"(d), "l"(src));
}
#define CP_COMMIT asm volatile("cp.async.commit_group;")
#define CP_WAIT0  asm volatile("cp.async.wait_group 0;")
#define CP_WAIT1  asm volatile("cp.async.wait_group 1;")

__device__ __forceinline__ float sqrt_ap(float f) {
    float r; asm("sqrt.approx.f32 %0, %1;" : "=f"(r) : "f"(f)); return r;
}
__device__ __forceinline__ void ldsm4(uint32_t r[4], uint32_t addr) {
    asm volatile("ldmatrix.sync.aligned.m8n8.x4.shared.b16 {%0,%1,%2,%3}, [%4];"
        : "=r"(r[0]), "=r"(r[1]), "=r"(r[2]), "=r"(r[3]) : "r"(addr));
}
__device__ __forceinline__ void mma_f16(float c[4], const uint32_t a[4],
                                        uint32_t b0, uint32_t b1) {
    asm volatile("mma.sync.aligned.m16n8k16.row.col.f32.f16.f16.f32 "
        "{%0,%1,%2,%3}, {%4,%5,%6,%7}, {%8,%9}, {%0,%1,%2,%3};"
        : "+f"(c[0]), "+f"(c[1]), "+f"(c[2]), "+f"(c[3])
        : "r"(a[0]), "r"(a[1]), "r"(a[2]), "r"(a[3]), "r"(b0), "r"(b1));
}

// ---------------- unified fp16 BT GEMM mainloop ----------------
#define F16_STAGE 32768
template<int NCH>
__device__ __forceinline__ void gemm_f16(const __half* __restrict__ A, int lda,
                                         const __half* __restrict__ Bg, int ldb,
                                         float acc[2][8][4], char* sm, uint32_t smU)
{
    const int tid = threadIdx.x;
    const int lane = tid & 31, warp = tid >> 5;
    const int wm = (warp & 3) * 32, wn = (warp >> 2) * 64;
    const int la7 = lane & 7, hi = (lane >> 4) & 1;

    #define GLD(s, k0) do {                                                          \
        char* st_ = sm + (s)*F16_STAGE;                                              \
        _Pragma("unroll")                                                            \
        for (int i_ = 0; i_ < 8; i_++) {                                             \
            int u_ = tid + i_*256;                                                   \
            if (u_ < 1024) {                                                         \
                int row_ = u_ >> 3, c_ = u_ & 7;                                     \
                cp16(st_ + row_*128 + ((c_ ^ (row_ & 7)) << 4),                      \
                     A + (size_t)row_*lda + (k0) + c_*8);                            \
            } else {                                                                 \
                int v_ = u_ - 1024;                                                  \
                int row_ = v_ >> 3, c_ = v_ & 7;                                     \
                cp16(st_ + 16384 + row_*128 + ((c_ ^ (row_ & 7)) << 4),              \
                     Bg + (size_t)row_*ldb + (k0) + c_*8);                           \
            }                                                                        \
        }                                                                            \
        CP_COMMIT;                                                                   \
    } while (0)

    GLD(0, 0);
    if (NCH > 1) GLD(1, 64);
    for (int t = 0; t < NCH; t++) {
        if (t + 1 < NCH) { CP_WAIT1; } else { CP_WAIT0; }
        __syncthreads();
        if (t + 2 < NCH) GLD((t + 2) % 3, (t + 2) * 64);
        const uint32_t aB = smU + (t % 3) * F16_STAGE;
        const uint32_t bB = aB + 16384;
        #pragma unroll
        for (int kk = 0; kk < 4; kk++) {
            uint32_t af[2][4];
            #pragma unroll
            for (int m = 0; m < 2; m++) {
                int row = wm + m*16 + (lane & 15);
                ldsm4(af[m], aB + row*128 + (((kk*2 + hi) ^ (row & 7)) << 4));
            }
            uint32_t bf[4][4];
            #pragma unroll
            for (int p = 0; p < 4; p++) {
                int row = wn + p*16 + la7 + (lane & 8);
                ldsm4(bf[p], bB + row*128 + (((kk*2 + hi) ^ (row & 7)) << 4));
            }
            #pragma unroll
            for (int m = 0; m < 2; m++)
                #pragma unroll
                for (int n = 0; n < 8; n++)
                    mma_f16(acc[m][n], af[m], bf[n>>1][n&1], bf[n>>1][(n&1)+2]);
        }
    }
    #undef GLD
}
#define F16_SMEM (3*F16_STAGE)

// ============================================================
// kfront: X fp32->fp16 (blocks 0..8191) + weights + R-zero (8192..8463)
// ============================================================
__global__ void kfront(const float* __restrict__ X, const float* __restrict__ Wq,
                       const float* __restrict__ Wh, const float* __restrict__ Ws) {
    const int bid = blockIdx.x;
    if (bid < 8192) {
        int i = (bid * 256 + threadIdx.x) * 4;
        float4 v = *(const float4*)(X + i);
        *(__half2*)(g_Xh + i)     = __floats2half2_rn(v.x, v.y);
        *(__half2*)(g_Xh + i + 2) = __floats2half2_rn(v.z, v.w);
        return;
    }
    int i = ((bid - 8192) * 256 + threadIdx.x) * 4;
    const float* s; __half* d; int j;
    if (i < 131072)      { s = Wq; d = g_Wqh; j = i; }
    else if (i < 196608) { s = Wh; d = g_Whh; j = i - 131072; }
    else if (i < 262144) { s = Ws; d = g_Wsh; j = i - 196608; }
    else if (i < 278528) { j = i - 262144; *(float4*)&g_R[j] = make_float4(0,0,0,0); return; }
    else return;
    float4 v = *(const float4*)(s + j);
    *(__half2*)(d + j)     = __floats2half2_rn(v.x, v.y);
    *(__half2*)(d + j + 2) = __floats2half2_rn(v.z, v.w);
}

// ============================================================
// K1F: fused Q-proj (x=0,1) and h (x=2)
// ============================================================
__global__ __launch_bounds__(256, 2) void k1f(const float* __restrict__ bq,
                                              const float* __restrict__ bh) {
    extern __shared__ char sm[];
    const uint32_t smU = (uint32_t)__cvta_generic_to_shared(sm);
    const int x = blockIdx.x, row0 = blockIdx.y * 128;
    const __half* A  = g_Xh + (size_t)row0 * XD;
    const __half* Bg = (x < 2) ? g_Wqh + (size_t)x * 128 * XD : g_Whh;
    float acc[2][8][4] = {};
    gemm_f16<XD/64>(A, XD, Bg, XD, acc, sm, smU);
    const int lane = threadIdx.x & 31, warp = threadIdx.x >> 5;
    const int wm = (warp & 3) * 32, wn = (warp >> 2) * 64;
    const int qr = lane >> 2, qc = lane & 3;
    if (x < 2) {
        const int col0 = x * 128;
        const int d = (col0 + wn) >> 6;
        #pragma unroll
        for (int m = 0; m < 2; m++)
            #pragma unroll
            for (int rr = 0; rr < 2; rr++) {
                int mrow = row0 + wm + m*16 + qr + rr*8;
                int l = mrow >> 4, b = mrow & 15;
                float s = 0.f;
                #pragma unroll
                for (int n = 0; n < 8; n++) {
                    int cg = col0 + wn + n*8 + 2*qc;
                    int q = cg & 63;
                    __half2 hv = __floats2half2_rn(acc[m][n][rr*2+0] + bq[cg],
                                                   acc[m][n][rr*2+1] + bq[cg+1]);
                    float vx = __half2float(__low2half(hv));
                    float vy = __half2float(__high2half(hv));
                    s += vx*vx + vy*vy;
                    *(__half2*)&g_Qh[(((size_t)d*BB + b)*LL + l)*QDIM + q] = hv;
                }
                s += __shfl_xor_sync(0xffffffffu, s, 1);
                s += __shfl_xor_sync(0xffffffffu, s, 2);
                if (qc == 0) g_sq[((size_t)d*BB + b)*LL + l] = s;
            }
    } else {
        #pragma unroll
        for (int m = 0; m < 2; m++)
            #pragma unroll
            for (int rr = 0; rr < 2; rr++) {
                int mrow = row0 + wm + m*16 + qr + rr*8;
                #pragma unroll
                for (int n = 0; n < 8; n++) {
                    int cg = wn + n*8 + 2*qc;
                    float v0 = 1.f / (1.f + __expf(-(acc[m][n][rr*2+0] + bh[cg])));
                    float v1 = 1.f / (1.f + __expf(-(acc[m][n][rr*2+1] + bh[cg+1])));
                    *(__half2*)&g_hh[(size_t)mrow * HL + cg] = __floats2half2_rn(v0, v1);
                }
            }
    }
}

// ============================================================
// role bodies for the merged mid kernel
// ============================================================
#define TLD 136
__device__ __forceinline__ void k2b_body(int colT, int rowT, const float* __restrict__ bs,
                                         char* sm, uint32_t smU) {
    const int row0 = rowT * 128, col0 = colT * 128;
    float acc[2][8][4] = {};
    gemm_f16<HL/64>(g_hh + (size_t)row0 * HL, HL, g_Wsh + (size_t)col0 * HL, HL, acc, sm, smU);
    const int tid = threadIdx.x;
    const int lane = tid & 31, warp = tid >> 5;
    const int wm = (warp & 3) * 32, wn = (warp >> 2) * 64;
    const int qr = lane >> 2, qc = lane & 3;
    __syncthreads();
    __half* T = (__half*)sm;
    #pragma unroll
    for (int m = 0; m < 2; m++)
        #pragma unroll
        for (int rr = 0; rr < 2; rr++) {
            int mr = wm + m*16 + qr + rr*8;
            #pragma unroll
            for (int n = 0; n < 8; n++) {
                int cc = wn + n*8 + 2*qc;
                T[cc*TLD + mr]     = __float2half(acc[m][n][rr*2+0] + bs[col0 + cc]);
                T[(cc+1)*TLD + mr] = __float2half(acc[m][n][rr*2+1] + bs[col0 + cc + 1]);
            }
        }
    __syncthreads();
    const int l0 = row0 >> 4;
    #pragma unroll
    for (int r = 0; r < 8; r++) {
        int idx = tid + r*256;
        int b = idx & 15, y = idx >> 4;
        __half tmp[8];
        #pragma unroll
        for (int lo = 0; lo < 8; lo++) tmp[lo] = T[y*TLD + lo*16 + b];
        *(uint4*)&g_SinT[((size_t)b*YD + col0 + y)*LL + l0] = *(uint4*)tmp;
    }
}

__device__ __forceinline__ void k5a_body(int b, int lc, char* sm) {
    const int t = threadIdx.x;
    const int q = t & 63, part = t >> 6;
    float s = 0.f;
    #pragma unroll
    for (int d = 0; d < ND; d++) {
        const __half* base = g_Qh + (((size_t)d*BB + b)*LL + lc*128) * QDIM;
        for (int l = part; l < 128; l += 4) s += __half2float(base[(size_t)l * QDIM + q]);
    }
    float* red = (float*)sm;
    red[t] = s;
    __syncthreads();
    if (part == 0)
        g_TQp[(b*8 + lc)*QDIM + q] = red[q] + red[64+q] + red[128+q] + red[192+q];
}

#define K3_STAGE 24576
__device__ __forceinline__ void k3_body(int jT, int iT, int bI,
                                        const float* __restrict__ mask,
                                        char* sm3, uint32_t smU) {
    const int i0 = iT * 128, j0 = jT * 64;
    const int tid = threadIdx.x;
    const int lane = tid & 31, warp = tid >> 5;
    const int wm = (warp & 3) * 32, wn = (warp >> 2) * 32;
    const int qr = lane >> 2, qc = lane & 3;

    #define K3_LD(s, d_) do {                                                        \
        const __half* Ab_ = g_Qh + (((size_t)(d_)*BB + bI)*LL + i0) * QDIM;          \
        const __half* Bb_ = g_Qh + (((size_t)(d_)*BB + bI)*LL + j0) * QDIM;          \
        char* st_ = sm3 + (s)*K3_STAGE;                                              \
        _Pragma("unroll")                                                            \
        for (int i_ = 0; i_ < 6; i_++) {                                             \
            int u_ = tid + i_*256;                                                   \
            if (u_ < 1024) {                                                         \
                int row_ = u_ >> 3, c_ = u_ & 7;                                     \
                cp16(st_ + row_*128 + ((c_ ^ (row_ & 7)) << 4),                      \
                     Ab_ + (size_t)row_*QDIM + c_*8);                                \
            } else {                                                                 \
                int v_ = u_ - 1024;                                                  \
                int row_ = v_ >> 3, c_ = v_ & 7;                                     \
                cp16(st_ + 16384 + row_*128 + ((c_ ^ (row_ & 7)) << 4),              \
                     Bb_ + (size_t)row_*QDIM + c_*8);                                \
            }                                                                        \
        }                                                                            \
        CP_COMMIT;                                                                   \
    } while (0)

    float logit[2][4][4] = {};
    K3_LD(0, 0);
    K3_LD(1, 1);
    const int la7 = lane & 7, hi = (lane >> 4) & 1;
    for (int d = 0; d < ND; d++) {
        if (d + 1 < ND) { CP_WAIT1; } else { CP_WAIT0; }
        __syncthreads();
        if (d + 2 < ND) K3_LD((d + 2) % 3, d + 2);
        const uint32_t aB = smU + (d % 3) * K3_STAGE;
        const uint32_t bB = aB + 16384;
        float acc[2][4][4] = {};
        #pragma unroll
        for (int kk = 0; kk < 4; kk++) {
            int sw = ((kk*2 + hi) ^ la7) << 4;
            uint32_t af[2][4];
            #pragma unroll
            for (int m = 0; m < 2; m++) {
                int row = wm + m*16 + (lane & 15);
                ldsm4(af[m], aB + row*128 + (((kk*2 + hi) ^ (row & 7)) << 4));
            }
            uint32_t bf[2][4];
            #pragma unroll
            for (int p = 0; p < 2; p++) {
                int row = wn + p*16 + la7 + (lane & 8);
                ldsm4(bf[p], bB + row*128 + sw);
            }
            #pragma unroll
            for (int m = 0; m < 2; m++)
                #pragma unroll
                for (int n = 0; n < 4; n++)
                    mma_f16(acc[m][n], af[m], bf[n>>1][n&1], bf[n>>1][(n&1)+2]);
        }
        const float sgn = (d & 1) ? -1.f : 1.f;
        const float* sqb = g_sq + ((size_t)d*BB + bI) * LL;
        #pragma unroll
        for (int m = 0; m < 2; m++)
            #pragma unroll
            for (int rr = 0; rr < 2; rr++) {
                int gi = i0 + wm + m*16 + qr + rr*8;
                float sqi = sqb[gi];
                #pragma unroll
                for (int n = 0; n < 4; n++) {
                    int gj = j0 + wn + n*8 + 2*qc;
                    float d20 = fmaxf(sqi + sqb[gj]   - 2.f*acc[m][n][rr*2+0], 0.f);
                    float d21 = fmaxf(sqi + sqb[gj+1] - 2.f*acc[m][n][rr*2+1], 0.f);
                    logit[m][n][rr*2+0] += (gi == gj)   ? 0.f : sgn * sqrt_ap(d20);
                    logit[m][n][rr*2+1] += (gi == gj+1) ? 0.f : sgn * sqrt_ap(d21);
                }
            }
    }
    #undef K3_LD
    #pragma unroll
    for (int m = 0; m < 2; m++)
        #pragma unroll
        for (int rr = 0; rr < 2; rr++) {
            int gi = i0 + wm + m*16 + qr + rr*8;
            float s = 0.f;
            #pragma unroll
            for (int n = 0; n < 4; n++) {
                int gj = j0 + wn + n*8 + 2*qc;
                float2 mv = *(const float2*)&mask[(size_t)gi * LL + gj];
                float e0 = __expf(logit[m][n][rr*2+0] * RSQRT512 + mv.x);
                float e1 = __expf(logit[m][n][rr*2+1] * RSQRT512 + mv.y);
                __half2 p2 = __floats2half2_rn(e0, e1);
                s += __half2float(__low2half(p2)) + __half2float(__high2half(p2));
                *(__half2*)&g_E[((size_t)bI*LL + gi)*LL + gj] = p2;
            }
            s += __shfl_xor_sync(0xffffffffu, s, 1);
            s += __shfl_xor_sync(0xffffffffu, s, 2);
            if (qc == 0) atomicAdd(&g_R[bI*LL + gi], s);
        }
}

// ============================================================
// kmid: blocks [0,512) k2b | [512,640) k5a | [640,2688) k3
// ============================================================
__global__ __launch_bounds__(256, 2) void kmid(const float* __restrict__ mask,
                                               const float* __restrict__ bs) {
    extern __shared__ char sm[];
    const uint32_t smU = (uint32_t)__cvta_generic_to_shared(sm);
    const int bid = blockIdx.x;
    if (bid < 512) {
        k2b_body(bid & 3, bid >> 2, bs, sm, smU);
    } else if (bid < 640) {
        int t = bid - 512;
        k5a_body(t & 15, t >> 4, sm);
    } else {
        int t = bid - 640;
        k3_body(t & 15, (t >> 4) & 7, t >> 7, mask, sm, smU);
    }
}

// ============================================================
// kend: blocks [0,512) k4 | [512,516) k5b
// ============================================================
__global__ __launch_bounds__(256, 2) void kend(float* __restrict__ out) {
    extern __shared__ char sm[];
    const uint32_t smU = (uint32_t)__cvta_generic_to_shared(sm);
    const int bid = blockIdx.x;
    if (bid < 512) {
        const int b = bid >> 5;
        const int row0 = ((bid >> 2) & 7) * 128, col0 = (bid & 3) * 128;
        float acc[2][8][4] = {};
        gemm_f16<LL/64>(g_E + (size_t)b*LL*LL + (size_t)row0*LL, LL,
                        g_SinT + ((size_t)b*YD + col0)*LL, LL, acc, sm, smU);
        const int lane = threadIdx.x & 31, warp = threadIdx.x >> 5;
        const int wm = (warp & 3) * 32, wn = (warp >> 2) * 64;
        const int qr = lane >> 2, qc = lane & 3;
        #pragma unroll
        for (int m = 0; m < 2; m++)
            #pragma unroll
            for (int rr = 0; rr < 2; rr++) {
                int row = row0 + wm + m*16 + qr + rr*8;
                float rinv = 1.f / g_R[b*LL + row];
                #pragma unroll
                for (int n = 0; n < 8; n++) {
                    int col = col0 + wn + n*8 + 2*qc;
                    float2 v;
                    v.x = acc[m][n][rr*2+0] * rinv;
                    v.y = acc[m][n][rr*2+1] * rinv;
                    *(float2*)&out[((size_t)b*LL + row)*YD + col] = v;
                }
            }
    } else {
        int idx = (bid - 512) * 256 + threadIdx.x;   // 0..1023
        int b = idx >> 6, q = idx & 63;
        float s = 0.f;
        #pragma unroll
        for (int lc = 0; lc < 8; lc++) s += g_TQp[(b*8 + lc)*QDIM + q];
        out[(size_t)BB*LL*YD + b*QDIM + q] = s * (1.f / (ND * (float)LL));
    }
}

// ============================================================
extern "C" void kernel_launch(void* const* d_in, const int* in_sizes, int n_in,
                              void* d_out, int out_size) {
    const float* X    = (const float*)d_in[0];
    const float* mask = (const float*)d_in[1];
    const float* Wq   = (const float*)d_in[2];
    const float* bq   = (const float*)d_in[3];
    const float* Wh   = (const float*)d_in[4];
    const float* bh   = (const float*)d_in[5];
    const float* Ws   = (const float*)d_in[6];
    const float* bs   = (const float*)d_in[7];
    float* out = (float*)d_out;

    cudaFuncSetAttribute(k1f,  cudaFuncAttributeMaxDynamicSharedMemorySize, F16_SMEM);
    cudaFuncSetAttribute(kmid, cudaFuncAttributeMaxDynamicSharedMemorySize, F16_SMEM);
    cudaFuncSetAttribute(kend, cudaFuncAttributeMaxDynamicSharedMemorySize, F16_SMEM);

    kfront<<<8464, 256>>>(X, Wq, Wh, Ws);
    k1f<<<dim3(3, 128), 256, F16_SMEM>>>(bq, bh);
    kmid<<<2688, 256, F16_SMEM>>>(mask, bs);
    kend<<<516, 256, F16_SMEM>>>(out);
}